// round 5
// baseline (speedup 1.0000x reference)
#include <cuda_runtime.h>
#include <cuda_bf16.h>
#include <cstdint>
#include <cstddef>

typedef __nv_bfloat16 bf16;

#define B_ 16
#define T_ 1024
#define P_ 48
#define S_ 12
#define A_ 24
#define D_ 768
#define DS_ 768
#define NROWS 4608   /* B*S*A */
#define CHUNK 128
#define NCHUNK 8     /* T/CHUNK */

// ---------------- fp32 scratch ------------------------------------------------
__device__ float g_vv[12582912];     // video_v [B,T,D]
__device__ float g_csum[12595200];   // chunk-local prefix sums [B,T+1,D]
__device__ float g_chunksum[98304];
__device__ float g_chunkoff[98304];
__device__ float g_score[B_ * P_];
__device__ float g_textseg[B_ * D_];
__device__ float g_videoseg[B_ * D_];
__device__ float g_q[B_ * D_];
__device__ float g_gi[10616832];     // [NROWS, 3*DS]
__device__ float g_gh[442368];       // [S*B, 3*DS]
__device__ float g_qh[3538944];      // [NROWS, DS]
__device__ float g_logits[NROWS];

// ---------------- bf16 scratch --------------------------------------------------
__device__ bf16 c_video[12582912];
__device__ bf16 c_para[589824];
__device__ bf16 c_question[12288];
__device__ bf16 c_atx[3538944];
__device__ bf16 c_abt[3538944];
__device__ bf16 b_wv1[589824], b_wv2[589824], b_wt1[589824], b_wt2[589824];
__device__ bf16 b_wp1[9437184], b_wp2[2359296];
__device__ bf16 b_wih[1769472], b_whh[1769472], b_wq1[589824];
__device__ bf16 b_h1[14155776];      // hidden scratch (max 4608*3072)
__device__ bf16 b_parat[589824];
__device__ bf16 b_at[3538944];
__device__ bf16 b_ab[3538944];
__device__ bf16 b_inputs[14155776];  // [NROWS, 4D]
__device__ bf16 b_xall[3538944];
__device__ bf16 b_hseq[147456];
__device__ bf16 b_hnew[3538944];

// ============================================================================
// bf16 tensor-core GEMM: C = act(A[M,K]bf16 @ W[K,N]bf16 + bias[N]f32)
// N multiple of 128, K multiple of 32, M arbitrary.
// 128x128x32 block tile, 4-stage cp.async pipeline, 8 warps (32x64 each),
// ldmatrix fragment loads (conflict-free padded strides), 2 CTAs/SM.
// ============================================================================
#define BKH 32
#define STAGES 4
#define SAK 40    /* As row stride (halves): 80B */
#define SWN 136   /* Ws row stride (halves): 272B */
#define ASZ (128 * SAK)   /* 5120 halves */
#define WSZ (BKH * SWN)   /* 4352 halves */
#define TG_SMEM (STAGES * (ASZ + WSZ) * 2)  /* 75776 bytes */

__device__ __forceinline__ void cp16(uint32_t dst_smem, const void* src, int sz) {
    asm volatile("cp.async.cg.shared.global [%0], [%1], 16, %2;\n" ::"r"(dst_smem),
                 "l"(src), "r"(sz));
}

__device__ __forceinline__ void ldsm4(uint32_t r[4], uint32_t addr) {
    asm volatile("ldmatrix.sync.aligned.m8n8.x4.shared.b16 {%0,%1,%2,%3},[%4];"
                 : "=r"(r[0]), "=r"(r[1]), "=r"(r[2]), "=r"(r[3])
                 : "r"(addr));
}

__device__ __forceinline__ void ldsm4t(uint32_t r[4], uint32_t addr) {
    asm volatile("ldmatrix.sync.aligned.m8n8.x4.trans.shared.b16 {%0,%1,%2,%3},[%4];"
                 : "=r"(r[0]), "=r"(r[1]), "=r"(r[2]), "=r"(r[3])
                 : "r"(addr));
}

__device__ __forceinline__ void mma_bf16(float c[4], const uint32_t a[4],
                                         const uint32_t b[2]) {
    asm volatile(
        "mma.sync.aligned.m16n8k16.row.col.f32.bf16.bf16.f32 "
        "{%0,%1,%2,%3},{%4,%5,%6,%7},{%8,%9},{%0,%1,%2,%3};"
        : "+f"(c[0]), "+f"(c[1]), "+f"(c[2]), "+f"(c[3])
        : "r"(a[0]), "r"(a[1]), "r"(a[2]), "r"(a[3]), "r"(b[0]), "r"(b[1]));
}

__device__ __forceinline__ void store2(float* C, size_t off, float x, float y) {
    *reinterpret_cast<float2*>(C + off) = make_float2(x, y);
}
__device__ __forceinline__ void store2(bf16* C, size_t off, float x, float y) {
    *reinterpret_cast<__nv_bfloat162*>(C + off) =
        __float22bfloat162_rn(make_float2(x, y));
}

template <int ACT, typename OT>
__global__ __launch_bounds__(256, 2) void hgemm(const bf16* __restrict__ A,
                                                const bf16* __restrict__ W,
                                                const float* __restrict__ bias,
                                                OT* __restrict__ C,
                                                int M, int N, int K) {
    extern __shared__ bf16 smh[];
    bf16* As = smh;                      // [STAGES][ASZ]  As[m][k]
    bf16* Ws = smh + STAGES * ASZ;       // [STAGES][WSZ]  Ws[k][n]

    const int tid = threadIdx.x;
    const int lane = tid & 31;
    const int warp = tid >> 5;
    const int warpM = (warp >> 1) * 32;  // 0,32,64,96
    const int warpN = (warp & 1) * 64;   // 0,64
    const int rowBase = blockIdx.y * 128;
    const int colBase = blockIdx.x * 128;
    const int KT = K / BKH;

    float acc[2][8][4];
#pragma unroll
    for (int i = 0; i < 2; i++)
#pragma unroll
        for (int j = 0; j < 8; j++)
#pragma unroll
            for (int k = 0; k < 4; k++) acc[i][j][k] = 0.f;

    auto loadStage = [&](int kt, int buf) {
        bf16* ad = As + buf * ASZ;
#pragma unroll
        for (int i = 0; i < 2; i++) {   // A: 128 rows x 4 x 16B
            int idx = tid + i * 256;
            int row = idx >> 2, q = idx & 3;
            int grow = rowBase + row;
            int crow = grow < M ? grow : 0;
            const bf16* src = A + (size_t)crow * K + kt * BKH + q * 8;
            uint32_t d = (uint32_t)__cvta_generic_to_shared(ad + row * SAK + q * 8);
            cp16(d, src, grow < M ? 16 : 0);
        }
        bf16* wd = Ws + buf * WSZ;
#pragma unroll
        for (int i = 0; i < 2; i++) {   // W: 32 rows x 16 x 16B
            int idx = tid + i * 256;
            int row = idx >> 4, q = idx & 15;
            const bf16* src = W + (size_t)(kt * BKH + row) * N + colBase + q * 8;
            uint32_t d = (uint32_t)__cvta_generic_to_shared(wd + row * SWN + q * 8);
            cp16(d, src, 16);
        }
    };

    // prologue: fill STAGES-1 stages
#pragma unroll
    for (int s = 0; s < STAGES - 1; s++) {
        if (s < KT) loadStage(s, s);
        asm volatile("cp.async.commit_group;\n");
    }

    for (int kt = 0; kt < KT; kt++) {
        const int buf = kt % STAGES;
        asm volatile("cp.async.wait_group %0;\n" ::"n"(STAGES - 2));
        __syncthreads();

        const bf16* a_s = As + buf * ASZ;
        const bf16* w_s = Ws + buf * WSZ;

#pragma unroll
        for (int ks = 0; ks < BKH / 16; ks++) {
            const int k0 = ks * 16;
            uint32_t af[2][4], bfr[8][2];
#pragma unroll
            for (int mi = 0; mi < 2; mi++) {
                uint32_t ad = (uint32_t)__cvta_generic_to_shared(
                    a_s + (size_t)(warpM + mi * 16 + (lane & 15)) * SAK + k0 +
                    ((lane >> 4) * 8));
                ldsm4(af[mi], ad);
            }
#pragma unroll
            for (int nb = 0; nb < 4; nb++) {
                uint32_t tmp[4];
                uint32_t wdaddr = (uint32_t)__cvta_generic_to_shared(
                    w_s + (size_t)(k0 + (lane & 15)) * SWN + warpN + nb * 16 +
                    ((lane >> 4) * 8));
                ldsm4t(tmp, wdaddr);
                bfr[2 * nb][0] = tmp[0];
                bfr[2 * nb][1] = tmp[1];
                bfr[2 * nb + 1][0] = tmp[2];
                bfr[2 * nb + 1][1] = tmp[3];
            }
#pragma unroll
            for (int mi = 0; mi < 2; mi++)
#pragma unroll
                for (int ni = 0; ni < 8; ni++) mma_bf16(acc[mi][ni], af[mi], bfr[ni]);
        }
        __syncthreads();

        // issue next stage load into the buffer just freed
        if (kt + STAGES - 1 < KT) loadStage(kt + STAGES - 1, (kt + STAGES - 1) % STAGES);
        asm volatile("cp.async.commit_group;\n");
    }

    // epilogue: bias + optional ReLU
#pragma unroll
    for (int mi = 0; mi < 2; mi++) {
        const int r0 = rowBase + warpM + mi * 16 + (lane >> 2);
#pragma unroll
        for (int ni = 0; ni < 8; ni++) {
            const int c = colBase + warpN + ni * 8 + 2 * (lane & 3);
            const float b0 = bias[c], b1 = bias[c + 1];
            float v0 = acc[mi][ni][0] + b0;
            float v1 = acc[mi][ni][1] + b1;
            float v2 = acc[mi][ni][2] + b0;
            float v3 = acc[mi][ni][3] + b1;
            if (ACT == 1) {
                v0 = fmaxf(v0, 0.f); v1 = fmaxf(v1, 0.f);
                v2 = fmaxf(v2, 0.f); v3 = fmaxf(v3, 0.f);
            }
            if (r0 < M) store2(C, (size_t)r0 * N + c, v0, v1);
            if (r0 + 8 < M) store2(C, (size_t)(r0 + 8) * N + c, v2, v3);
        }
    }
}

// ---------------- conversion kernel -------------------------------------------
__global__ void cvt32_kernel(const float* __restrict__ in, bf16* __restrict__ out,
                             int n) {
    int i = (blockIdx.x * blockDim.x + threadIdx.x) * 4;
    if (i >= n) return;
    float4 v = *reinterpret_cast<const float4*>(in + i);
    *reinterpret_cast<__nv_bfloat162*>(out + i) =
        __float22bfloat162_rn(make_float2(v.x, v.y));
    *reinterpret_cast<__nv_bfloat162*>(out + i + 2) =
        __float22bfloat162_rn(make_float2(v.z, v.w));
}

// ---------------- small kernels ----------------------------------------------
__global__ void softmax_paras_kernel(const float* __restrict__ ps,
                                     float* __restrict__ score) {
    int b = threadIdx.x;
    if (b >= B_) return;
    float mx = -1e30f;
    for (int p = 0; p < P_; p++) mx = fmaxf(mx, ps[b * P_ + p]);
    float sum = 0.f;
    for (int p = 0; p < P_; p++) sum += expf(ps[b * P_ + p] - mx);
    float inv = 1.f / sum;
    for (int p = 0; p < P_; p++) score[b * P_ + p] = expf(ps[b * P_ + p] - mx) * inv;
}

__global__ void weighted_sum_kernel(const float* __restrict__ score,
                                    const bf16* __restrict__ x,   // [B,P,D]
                                    float* __restrict__ out) {    // [B,D]
    int b = blockIdx.x, d = threadIdx.x;
    float acc = 0.f;
    for (int p = 0; p < P_; p++)
        acc += score[b * P_ + p] *
               __bfloat162float(x[((size_t)(b * P_ + p)) * D_ + d]);
    out[b * D_ + d] = acc;
}

__global__ void csum_phase1(const float* __restrict__ vv,
                            float* __restrict__ csum,
                            float* __restrict__ chunksum) {
    int b = blockIdx.x / NCHUNK, c = blockIdx.x % NCHUNK;
    int d = threadIdx.x;
    float run = 0.f;
    int tbase = c * CHUNK;
    for (int i = 0; i < CHUNK; i++) {
        run += vv[((size_t)b * T_ + tbase + i) * D_ + d];
        csum[((size_t)b * (T_ + 1) + tbase + i + 1) * D_ + d] = run;
    }
    chunksum[(b * NCHUNK + c) * D_ + d] = run;
}

__global__ void csum_phase2(const float* __restrict__ chunksum,
                            float* __restrict__ chunkoff) {
    int b = blockIdx.x, d = threadIdx.x;
    float run = 0.f;
    for (int c = 0; c < NCHUNK; c++) {
        chunkoff[(b * NCHUNK + c) * D_ + d] = run;
        run += chunksum[(b * NCHUNK + c) * D_ + d];
    }
}

__device__ __forceinline__ float get_csum(const float* csum, const float* coff,
                                          int b, int t, int d) {
    if (t == 0) return 0.f;
    int c = (t - 1) >> 7;  // CHUNK=128
    return csum[((size_t)b * (T_ + 1) + t) * D_ + d] +
           coff[(b * NCHUNK + c) * D_ + d];
}

__global__ void seg_kernel(const float* __restrict__ vv,
                           const float* __restrict__ csum,
                           const float* __restrict__ coff,
                           const float* __restrict__ score,
                           const int* __restrict__ starts,
                           const int* __restrict__ ends,
                           float* __restrict__ video_seg) {
    int b = blockIdx.x, d = threadIdx.x;
    float acc = 0.f;
    for (int p = 0; p < P_; p++) {
        int s = starts[b * P_ + p], e = ends[b * P_ + p];
        float val;
        if (s >= e) {
            val = vv[((size_t)b * T_ + s) * D_ + d];
        } else {
            float ce = get_csum(csum, coff, b, e, d);
            float cs = get_csum(csum, coff, b, s, d);
            val = (ce - cs) / (float)(e - s);
        }
        acc += score[b * P_ + p] * val;
    }
    video_seg[b * D_ + d] = acc;
}

__global__ void concat_kernel(const float* __restrict__ video_seg,
                              const float* __restrict__ text_seg,
                              const float* __restrict__ q,
                              const bf16* __restrict__ at,
                              const bf16* __restrict__ ab,
                              bf16* __restrict__ out) {
    int r = blockIdx.x;  // (b*S+s)*A+a
    int d = threadIdx.x;
    int b = r / (S_ * A_);
    size_t base = (size_t)r * (4 * D_);
    out[base + d] = __float2bfloat16_rn(video_seg[b * D_ + d]);
    out[base + D_ + d] = __float2bfloat16_rn(text_seg[b * D_ + d]);
    out[base + 2 * D_ + d] = __float2bfloat16_rn(
        q[b * D_ + d] + __bfloat162float(at[(size_t)r * D_ + d]));
    out[base + 3 * D_ + d] = ab[(size_t)r * D_ + d];
}

__global__ void hseq_kernel(const bf16* __restrict__ xall,
                            const int* __restrict__ label,
                            const float* __restrict__ state0,
                            bf16* __restrict__ hseq) {
    int sb = blockIdx.x;          // s*B + b
    int s = sb / B_, b = sb % B_;
    int d = threadIdx.x;
    bf16 v;
    if (s == 0) {
        v = __float2bfloat16_rn(state0[d]);
    } else {
        int lab = label[b * S_ + (s - 1)];
        v = xall[(size_t)((b * S_ + (s - 1)) * A_ + lab) * DS_ + d];
    }
    hseq[(size_t)sb * DS_ + d] = v;
}

__global__ void gru_kernel(const float* __restrict__ gi,
                           const float* __restrict__ gh,
                           const bf16* __restrict__ hseq,
                           bf16* __restrict__ hnew) {
    int r = blockIdx.x;  // (b*S+s)*A+a
    int d = threadIdx.x;
    int bs = r / A_;
    int b = bs / S_, s = bs % S_;
    int sb = s * B_ + b;
    size_t gbase = (size_t)r * (3 * DS_);
    size_t hbase = (size_t)sb * (3 * DS_);
    float ir = gi[gbase + d];
    float iz = gi[gbase + DS_ + d];
    float in = gi[gbase + 2 * DS_ + d];
    float hr = gh[hbase + d];
    float hz = gh[hbase + DS_ + d];
    float hn = gh[hbase + 2 * DS_ + d];
    float h = __bfloat162float(hseq[(size_t)sb * DS_ + d]);
    float rg = 1.f / (1.f + expf(-(ir + hr)));
    float z = 1.f / (1.f + expf(-(iz + hz)));
    float n = tanhf(in + rg * hn);
    hnew[(size_t)r * DS_ + d] = __float2bfloat16_rn((1.f - z) * n + z * h);
}

__global__ void logits_kernel(const float* __restrict__ qh,
                              const float* __restrict__ wq2,
                              const float* __restrict__ bq2,
                              float* __restrict__ logits) {
    int warp = (blockIdx.x * blockDim.x + threadIdx.x) >> 5;
    int lane = threadIdx.x & 31;
    if (warp >= NROWS) return;
    float sum = 0.f;
    for (int d = lane; d < DS_; d += 32)
        sum += qh[(size_t)warp * DS_ + d] * wq2[d];
#pragma unroll
    for (int o = 16; o; o >>= 1) sum += __shfl_down_sync(0xffffffffu, sum, o);
    if (lane == 0) logits[warp] = sum + bq2[0];
}

__global__ void loss_kernel(const float* __restrict__ logits,
                            const int* __restrict__ label,
                            float* __restrict__ out) {
    __shared__ float sh[S_ * B_];
    int t = threadIdx.x;  // 0..191
    int b = t / S_, s = t % S_;
    const float* l = &logits[(size_t)(b * S_ + s) * A_];
    float mx = -1e30f;
    for (int a = 0; a < A_; a++) mx = fmaxf(mx, l[a]);
    float sum = 0.f;
    for (int a = 0; a < A_; a++) sum += expf(l[a] - mx);
    float lse = mx + logf(sum);
    int lab = label[b * S_ + s];
    sh[t] = lse - l[lab];
    __syncthreads();
    if (t == 0) {
        float tot = 0.f;
        for (int i = 0; i < S_ * B_; i++) tot += sh[i];
        out[0] = tot / (float)(S_ * B_);
    }
}

// ---------------- launch ------------------------------------------------------
static inline void cvt(const float* in, bf16* out, int n) {
    cvt32_kernel<<<(n / 4 + 255) / 256, 256>>>(in, out, n);
}

template <typename OT>
static inline void run_gemm(const bf16* A, const bf16* W, const float* bias,
                            OT* C, int M, int N, int K, bool relu) {
    dim3 grid(N / 128, (M + 127) / 128);
    if (relu) {
        cudaFuncSetAttribute(hgemm<1, OT>,
                             cudaFuncAttributeMaxDynamicSharedMemorySize, TG_SMEM);
        hgemm<1, OT><<<grid, 256, TG_SMEM>>>(A, W, bias, C, M, N, K);
    } else {
        cudaFuncSetAttribute(hgemm<0, OT>,
                             cudaFuncAttributeMaxDynamicSharedMemorySize, TG_SMEM);
        hgemm<0, OT><<<grid, 256, TG_SMEM>>>(A, W, bias, C, M, N, K);
    }
}

extern "C" void kernel_launch(void* const* d_in, const int* in_sizes, int n_in,
                              void* d_out, int out_size) {
    const float* video = (const float*)d_in[0];
    const float* para = (const float*)d_in[1];
    const float* question = (const float*)d_in[2];
    const float* a_texts = (const float*)d_in[3];
    const float* a_buttons = (const float*)d_in[4];
    const float* paras_score = (const float*)d_in[5];
    const int* starts = (const int*)d_in[6];
    const int* ends = (const int*)d_in[7];
    const int* label = (const int*)d_in[8];
    const float* wv1 = (const float*)d_in[9];
    const float* bv1 = (const float*)d_in[10];
    const float* wv2 = (const float*)d_in[11];
    const float* bv2 = (const float*)d_in[12];
    const float* wt1 = (const float*)d_in[13];
    const float* bt1 = (const float*)d_in[14];
    const float* wt2 = (const float*)d_in[15];
    const float* bt2 = (const float*)d_in[16];
    const float* wp1 = (const float*)d_in[17];
    const float* bp1 = (const float*)d_in[18];
    const float* wp2 = (const float*)d_in[19];
    const float* bp2 = (const float*)d_in[20];
    const float* w_ih = (const float*)d_in[21];
    const float* b_ih = (const float*)d_in[22];
    const float* w_hh = (const float*)d_in[23];
    const float* b_hh = (const float*)d_in[24];
    const float* wq1 = (const float*)d_in[25];
    const float* bq1 = (const float*)d_in[26];
    const float* wq2 = (const float*)d_in[27];
    const float* bq2 = (const float*)d_in[28];
    const float* state0 = (const float*)d_in[29];
    float* out = (float*)d_out;

    float *p_vv, *p_csum, *p_chs, *p_cho, *p_score, *p_tseg, *p_vseg, *p_q,
        *p_gi, *p_gh, *p_qh, *p_logits;
    cudaGetSymbolAddress((void**)&p_vv, g_vv);
    cudaGetSymbolAddress((void**)&p_csum, g_csum);
    cudaGetSymbolAddress((void**)&p_chs, g_chunksum);
    cudaGetSymbolAddress((void**)&p_cho, g_chunkoff);
    cudaGetSymbolAddress((void**)&p_score, g_score);
    cudaGetSymbolAddress((void**)&p_tseg, g_textseg);
    cudaGetSymbolAddress((void**)&p_vseg, g_videoseg);
    cudaGetSymbolAddress((void**)&p_q, g_q);
    cudaGetSymbolAddress((void**)&p_gi, g_gi);
    cudaGetSymbolAddress((void**)&p_gh, g_gh);
    cudaGetSymbolAddress((void**)&p_qh, g_qh);
    cudaGetSymbolAddress((void**)&p_logits, g_logits);

    bf16 *q_video, *q_para, *q_question, *q_atx, *q_abt;
    bf16 *qw_v1, *qw_v2, *qw_t1, *qw_t2, *qw_p1, *qw_p2, *qw_ih, *qw_hh, *qw_q1;
    bf16 *q_h1, *q_parat, *q_at, *q_ab, *q_inputs, *q_xall, *q_hseq, *q_hnew;
    cudaGetSymbolAddress((void**)&q_video, c_video);
    cudaGetSymbolAddress((void**)&q_para, c_para);
    cudaGetSymbolAddress((void**)&q_question, c_question);
    cudaGetSymbolAddress((void**)&q_atx, c_atx);
    cudaGetSymbolAddress((void**)&q_abt, c_abt);
    cudaGetSymbolAddress((void**)&qw_v1, b_wv1);
    cudaGetSymbolAddress((void**)&qw_v2, b_wv2);
    cudaGetSymbolAddress((void**)&qw_t1, b_wt1);
    cudaGetSymbolAddress((void**)&qw_t2, b_wt2);
    cudaGetSymbolAddress((void**)&qw_p1, b_wp1);
    cudaGetSymbolAddress((void**)&qw_p2, b_wp2);
    cudaGetSymbolAddress((void**)&qw_ih, b_wih);
    cudaGetSymbolAddress((void**)&qw_hh, b_whh);
    cudaGetSymbolAddress((void**)&qw_q1, b_wq1);
    cudaGetSymbolAddress((void**)&q_h1, b_h1);
    cudaGetSymbolAddress((void**)&q_parat, b_parat);
    cudaGetSymbolAddress((void**)&q_at, b_at);
    cudaGetSymbolAddress((void**)&q_ab, b_ab);
    cudaGetSymbolAddress((void**)&q_inputs, b_inputs);
    cudaGetSymbolAddress((void**)&q_xall, b_xall);
    cudaGetSymbolAddress((void**)&q_hseq, b_hseq);
    cudaGetSymbolAddress((void**)&q_hnew, b_hnew);

    // 0. fp32 -> bf16 conversions (inputs + weights)
    cvt(video, q_video, B_ * T_ * D_);
    cvt(para, q_para, B_ * P_ * D_);
    cvt(question, q_question, B_ * D_);
    cvt(a_texts, q_atx, NROWS * D_);
    cvt(a_buttons, q_abt, NROWS * D_);
    cvt(wv1, qw_v1, D_ * D_);
    cvt(wv2, qw_v2, D_ * D_);
    cvt(wt1, qw_t1, D_ * D_);
    cvt(wt2, qw_t2, D_ * D_);
    cvt(wp1, qw_p1, 4 * D_ * 4 * D_);
    cvt(wp2, qw_p2, 4 * D_ * DS_);
    cvt(w_ih, qw_ih, DS_ * 3 * DS_);
    cvt(w_hh, qw_hh, DS_ * 3 * DS_);
    cvt(wq1, qw_q1, DS_ * DS_);

    // 1. softmax over paragraph scores
    softmax_paras_kernel<<<1, 32>>>(paras_score, p_score);

    // 2. para MLP (text weights) -> text_seg
    run_gemm(q_para, qw_t1, bt1, q_h1, B_ * P_, D_, D_, true);
    run_gemm(q_h1, qw_t2, bt2, q_parat, B_ * P_, D_, D_, false);
    weighted_sum_kernel<<<B_, D_>>>(p_score, q_parat, p_tseg);

    // 3. video MLP (video weights) -> vv (fp32 for prefix sums)
    run_gemm(q_video, qw_v1, bv1, q_h1, B_ * T_, D_, D_, true);
    run_gemm(q_h1, qw_v2, bv2, p_vv, B_ * T_, D_, D_, false);

    // 4. chunked prefix sums + segment means -> video_seg
    csum_phase1<<<B_ * NCHUNK, D_>>>(p_vv, p_csum, p_chs);
    csum_phase2<<<B_, D_>>>(p_chs, p_cho);
    seg_kernel<<<B_, D_>>>(p_vv, p_csum, p_cho, p_score, starts, ends, p_vseg);

    // 5. question MLP (text weights)
    run_gemm(q_question, qw_t1, bt1, q_h1, B_, D_, D_, true);
    run_gemm(q_h1, qw_t2, bt2, p_q, B_, D_, D_, false);

    // 6. answer-text MLP (text weights), answer-button MLP (video weights)
    run_gemm(q_atx, qw_t1, bt1, q_h1, NROWS, D_, D_, true);
    run_gemm(q_h1, qw_t2, bt2, q_at, NROWS, D_, D_, false);
    run_gemm(q_abt, qw_v1, bv1, q_h1, NROWS, D_, D_, true);
    run_gemm(q_h1, qw_v2, bv2, q_ab, NROWS, D_, D_, false);

    // 7. concat -> fusion MLP -> x_all
    concat_kernel<<<NROWS, D_>>>(p_vseg, p_tseg, p_q, q_at, q_ab, q_inputs);
    run_gemm(q_inputs, qw_p1, bp1, q_h1, NROWS, 4 * D_, 4 * D_, true);
    run_gemm(q_h1, qw_p2, bp2, q_xall, NROWS, DS_, 4 * D_, false);

    // 8. teacher-forced hidden states + GRU gates
    hseq_kernel<<<S_ * B_, DS_>>>(q_xall, label, state0, q_hseq);
    run_gemm(q_xall, qw_ih, b_ih, p_gi, NROWS, 3 * DS_, DS_, false);
    run_gemm(q_hseq, qw_hh, b_hh, p_gh, S_ * B_, 3 * DS_, DS_, false);
    gru_kernel<<<NROWS, DS_>>>(p_gi, p_gh, q_hseq, q_hnew);

    // 9. logits MLP + loss
    run_gemm(q_hnew, qw_q1, bq1, p_qh, NROWS, DS_, DS_, true);
    logits_kernel<<<(NROWS * 32 + 255) / 256, 256>>>(p_qh, wq2, bq2, p_logits);
    loss_kernel<<<1, S_ * B_>>>(p_logits, label, out);
}

// round 6
// speedup vs baseline: 1.2576x; 1.2576x over previous
#include <cuda_runtime.h>
#include <cuda_bf16.h>
#include <cstdint>
#include <cstddef>

typedef __nv_bfloat16 bf16;

#define B_ 16
#define T_ 1024
#define P_ 48
#define S_ 12
#define A_ 24
#define D_ 768
#define DS_ 768
#define NROWS 4608   /* B*S*A */
#define SA_ 288      /* S*A rows per batch element */
#define CHUNK 128
#define NCHUNK 8     /* T/CHUNK */

// ---------------- fp32 scratch ------------------------------------------------
__device__ float g_vv[12582912];     // video_v [B,T,D]
__device__ float g_csum[12595200];   // chunk-local prefix sums [B,T+1,D]
__device__ float g_chunksum[98304];
__device__ float g_chunkoff[98304];
__device__ float g_score[B_ * P_];
__device__ float g_textseg[B_ * D_];
__device__ float g_videoseg[B_ * D_];
__device__ float g_pre[B_ * 3072];   // [16, 3072] fused row-bias (incl bp1)
__device__ float g_gi[10616832];     // [NROWS, 3*DS]
__device__ float g_gh[442368];       // [S*B, 3*DS]
__device__ float g_qh[3538944];      // [NROWS, DS]
__device__ float g_logits[NROWS];

// ---------------- bf16 scratch --------------------------------------------------
__device__ bf16 c_video[12582912];
__device__ bf16 c_tin[602112];       // [para(768) | question(16)] x 768
__device__ bf16 c_atx[3538944];
__device__ bf16 c_abt[3538944];
__device__ bf16 b_wv1[589824], b_wv2[589824], b_wt1[589824], b_wt2[589824];
__device__ bf16 b_wp1[9437184], b_wp2[2359296];
__device__ bf16 b_wih[1769472], b_whh[1769472], b_wq1[589824];
__device__ bf16 b_h1[14155776];      // hidden scratch (max 4608*3072)
__device__ bf16 b_tout[602112];      // [784, 768] text-MLP out (parat | q)
__device__ bf16 b_comb[7077888];     // [NROWS, 1536] = [at | ab]
__device__ bf16 b_preA[B_ * 2304];   // [16, 2304] = [vseg | tseg | q]
__device__ bf16 b_xall[3538944];
__device__ bf16 b_hseq[147456];
__device__ bf16 b_hnew[3538944];

// ============================================================================
// bf16 tensor-core GEMM: C = epi(A[M,K]bf16 @ W[K,N]bf16)
// ACT: 0 = +bias[N], 1 = relu(+bias[N]), 2 = relu(+bias[(r/288)*N + n])
// N multiple of 128, K multiple of 64, M arbitrary. ldc = C row stride.
// 128x128x64 block tile, 8 warps (64x32 each), cp.async double buffering,
// ldmatrix fragment loads (conflict-free padded strides).
// ============================================================================
#define BKH 64
#define SAK 72    /* As row stride (halves) */
#define SWN 136   /* Ws row stride (halves) */
#define ASZ (128 * SAK)
#define WSZ (BKH * SWN)
#define TG_SMEM ((2 * ASZ + 2 * WSZ) * 2)  /* 71680 bytes */

__device__ __forceinline__ void cp16(uint32_t dst_smem, const void* src, int sz) {
    asm volatile("cp.async.cg.shared.global [%0], [%1], 16, %2;\n" ::"r"(dst_smem),
                 "l"(src), "r"(sz));
}

__device__ __forceinline__ void ldsm4(uint32_t r[4], uint32_t addr) {
    asm volatile("ldmatrix.sync.aligned.m8n8.x4.shared.b16 {%0,%1,%2,%3},[%4];"
                 : "=r"(r[0]), "=r"(r[1]), "=r"(r[2]), "=r"(r[3])
                 : "r"(addr));
}

__device__ __forceinline__ void ldsm4t(uint32_t r[4], uint32_t addr) {
    asm volatile("ldmatrix.sync.aligned.m8n8.x4.trans.shared.b16 {%0,%1,%2,%3},[%4];"
                 : "=r"(r[0]), "=r"(r[1]), "=r"(r[2]), "=r"(r[3])
                 : "r"(addr));
}

__device__ __forceinline__ void mma_bf16(float c[4], const uint32_t a[4],
                                         const uint32_t b[2]) {
    asm volatile(
        "mma.sync.aligned.m16n8k16.row.col.f32.bf16.bf16.f32 "
        "{%0,%1,%2,%3},{%4,%5,%6,%7},{%8,%9},{%0,%1,%2,%3};"
        : "+f"(c[0]), "+f"(c[1]), "+f"(c[2]), "+f"(c[3])
        : "r"(a[0]), "r"(a[1]), "r"(a[2]), "r"(a[3]), "r"(b[0]), "r"(b[1]));
}

__device__ __forceinline__ void store2(float* C, size_t off, float x, float y) {
    *reinterpret_cast<float2*>(C + off) = make_float2(x, y);
}
__device__ __forceinline__ void store2(bf16* C, size_t off, float x, float y) {
    *reinterpret_cast<__nv_bfloat162*>(C + off) =
        __float22bfloat162_rn(make_float2(x, y));
}

template <int ACT, typename OT>
__global__ __launch_bounds__(256) void hgemm(const bf16* __restrict__ A,
                                             const bf16* __restrict__ W,
                                             const float* __restrict__ bias,
                                             OT* __restrict__ C,
                                             int M, int N, int K, int ldc) {
    extern __shared__ bf16 smh[];
    bf16* As = smh;               // [2][ASZ]  As[m][k]
    bf16* Ws = smh + 2 * ASZ;     // [2][WSZ]  Ws[k][n]

    const int tid = threadIdx.x;
    const int lane = tid & 31;
    const int warp = tid >> 5;
    const int warpM = (warp >> 2) * 64;
    const int warpN = (warp & 3) * 32;
    const int rowBase = blockIdx.y * 128;
    const int colBase = blockIdx.x * 128;
    const int KT = K / BKH;

    float acc[4][4][4];
#pragma unroll
    for (int i = 0; i < 4; i++)
#pragma unroll
        for (int j = 0; j < 4; j++)
#pragma unroll
            for (int k = 0; k < 4; k++) acc[i][j][k] = 0.f;

    auto loadTile = [&](int kt, int buf) {
        bf16* ad = As + buf * ASZ;
#pragma unroll
        for (int i = 0; i < 4; i++) {
            int idx = tid + i * 256;
            int row = idx >> 3, oct = idx & 7;
            int grow = rowBase + row;
            int crow = grow < M ? grow : 0;
            const bf16* src = A + (size_t)crow * K + kt * BKH + oct * 8;
            uint32_t d = (uint32_t)__cvta_generic_to_shared(ad + row * SAK + oct * 8);
            cp16(d, src, grow < M ? 16 : 0);
        }
        bf16* wd = Ws + buf * WSZ;
#pragma unroll
        for (int i = 0; i < 4; i++) {
            int idx = tid + i * 256;
            int row = idx >> 4, oct = idx & 15;
            const bf16* src = W + (size_t)(kt * BKH + row) * N + colBase + oct * 8;
            uint32_t d = (uint32_t)__cvta_generic_to_shared(wd + row * SWN + oct * 8);
            cp16(d, src, 16);
        }
    };

    loadTile(0, 0);
    asm volatile("cp.async.commit_group;\n");

    for (int kt = 0; kt < KT; kt++) {
        const int buf = kt & 1;
        if (kt + 1 < KT) {
            loadTile(kt + 1, buf ^ 1);
            asm volatile("cp.async.commit_group;\n");
            asm volatile("cp.async.wait_group 1;\n");
        } else {
            asm volatile("cp.async.wait_group 0;\n");
        }
        __syncthreads();

        const bf16* a_s = As + buf * ASZ;
        const bf16* w_s = Ws + buf * WSZ;

#pragma unroll
        for (int ks = 0; ks < BKH / 16; ks++) {
            const int k0 = ks * 16;
            uint32_t af[4][4], bfr[4][2];
#pragma unroll
            for (int mi = 0; mi < 4; mi++) {
                uint32_t ad = (uint32_t)__cvta_generic_to_shared(
                    a_s + (size_t)(warpM + mi * 16 + (lane & 15)) * SAK + k0 +
                    ((lane >> 4) * 8));
                ldsm4(af[mi], ad);
            }
#pragma unroll
            for (int nb = 0; nb < 2; nb++) {
                uint32_t tmp[4];
                uint32_t wdaddr = (uint32_t)__cvta_generic_to_shared(
                    w_s + (size_t)(k0 + (lane & 15)) * SWN + warpN + nb * 16 +
                    ((lane >> 4) * 8));
                ldsm4t(tmp, wdaddr);
                bfr[2 * nb][0] = tmp[0];
                bfr[2 * nb][1] = tmp[1];
                bfr[2 * nb + 1][0] = tmp[2];
                bfr[2 * nb + 1][1] = tmp[3];
            }
#pragma unroll
            for (int mi = 0; mi < 4; mi++)
#pragma unroll
                for (int ni = 0; ni < 4; ni++) mma_bf16(acc[mi][ni], af[mi], bfr[ni]);
        }
        __syncthreads();
    }

    // epilogue
#pragma unroll
    for (int mi = 0; mi < 4; mi++) {
        const int r0 = rowBase + warpM + mi * 16 + (lane >> 2);
        const float* br0;
        const float* br8;
        if (ACT == 2) {
            int g0 = r0 / SA_;
            int g8 = (r0 + 8) / SA_;
            if (g0 > B_ - 1) g0 = B_ - 1;
            if (g8 > B_ - 1) g8 = B_ - 1;
            br0 = bias + (size_t)g0 * N;
            br8 = bias + (size_t)g8 * N;
        } else {
            br0 = bias;
            br8 = bias;
        }
#pragma unroll
        for (int ni = 0; ni < 4; ni++) {
            const int c = colBase + warpN + ni * 8 + 2 * (lane & 3);
            float v0 = acc[mi][ni][0] + br0[c];
            float v1 = acc[mi][ni][1] + br0[c + 1];
            float v2 = acc[mi][ni][2] + br8[c];
            float v3 = acc[mi][ni][3] + br8[c + 1];
            if (ACT >= 1) {
                v0 = fmaxf(v0, 0.f); v1 = fmaxf(v1, 0.f);
                v2 = fmaxf(v2, 0.f); v3 = fmaxf(v3, 0.f);
            }
            if (r0 < M) store2(C, (size_t)r0 * ldc + c, v0, v1);
            if (r0 + 8 < M) store2(C, (size_t)(r0 + 8) * ldc + c, v2, v3);
        }
    }
}

// ---------------- conversion kernel -------------------------------------------
__global__ void cvt32_kernel(const float* __restrict__ in, bf16* __restrict__ out,
                             int n) {
    int i = (blockIdx.x * blockDim.x + threadIdx.x) * 4;
    if (i >= n) return;
    float4 v = *reinterpret_cast<const float4*>(in + i);
    *reinterpret_cast<__nv_bfloat162*>(out + i) =
        __float22bfloat162_rn(make_float2(v.x, v.y));
    *reinterpret_cast<__nv_bfloat162*>(out + i + 2) =
        __float22bfloat162_rn(make_float2(v.z, v.w));
}

// ---------------- small kernels ----------------------------------------------
__global__ void softmax_paras_kernel(const float* __restrict__ ps,
                                     float* __restrict__ score) {
    int b = threadIdx.x;
    if (b >= B_) return;
    float mx = -1e30f;
    for (int p = 0; p < P_; p++) mx = fmaxf(mx, ps[b * P_ + p]);
    float sum = 0.f;
    for (int p = 0; p < P_; p++) sum += expf(ps[b * P_ + p] - mx);
    float inv = 1.f / sum;
    for (int p = 0; p < P_; p++) score[b * P_ + p] = expf(ps[b * P_ + p] - mx) * inv;
}

__global__ void weighted_sum_kernel(const float* __restrict__ score,
                                    const bf16* __restrict__ x,   // [B,P,D]
                                    float* __restrict__ out) {    // [B,D]
    int b = blockIdx.x, d = threadIdx.x;
    float acc = 0.f;
    for (int p = 0; p < P_; p++)
        acc += score[b * P_ + p] *
               __bfloat162float(x[((size_t)(b * P_ + p)) * D_ + d]);
    out[b * D_ + d] = acc;
}

__global__ void csum_phase1(const float* __restrict__ vv,
                            float* __restrict__ csum,
                            float* __restrict__ chunksum) {
    int b = blockIdx.x / NCHUNK, c = blockIdx.x % NCHUNK;
    int d = threadIdx.x;
    float run = 0.f;
    int tbase = c * CHUNK;
    for (int i = 0; i < CHUNK; i++) {
        run += vv[((size_t)b * T_ + tbase + i) * D_ + d];
        csum[((size_t)b * (T_ + 1) + tbase + i + 1) * D_ + d] = run;
    }
    chunksum[(b * NCHUNK + c) * D_ + d] = run;
}

__global__ void csum_phase2(const float* __restrict__ chunksum,
                            float* __restrict__ chunkoff) {
    int b = blockIdx.x, d = threadIdx.x;
    float run = 0.f;
    for (int c = 0; c < NCHUNK; c++) {
        chunkoff[(b * NCHUNK + c) * D_ + d] = run;
        run += chunksum[(b * NCHUNK + c) * D_ + d];
    }
}

__device__ __forceinline__ float get_csum(const float* csum, const float* coff,
                                          int b, int t, int d) {
    if (t == 0) return 0.f;
    int c = (t - 1) >> 7;  // CHUNK=128
    return csum[((size_t)b * (T_ + 1) + t) * D_ + d] +
           coff[(b * NCHUNK + c) * D_ + d];
}

__global__ void seg_kernel(const float* __restrict__ vv,
                           const float* __restrict__ csum,
                           const float* __restrict__ coff,
                           const float* __restrict__ score,
                           const int* __restrict__ starts,
                           const int* __restrict__ ends,
                           float* __restrict__ video_seg) {
    int b = blockIdx.x, d = threadIdx.x;
    float acc = 0.f;
    for (int p = 0; p < P_; p++) {
        int s = starts[b * P_ + p], e = ends[b * P_ + p];
        float val;
        if (s >= e) {
            val = vv[((size_t)b * T_ + s) * D_ + d];
        } else {
            float ce = get_csum(csum, coff, b, e, d);
            float cs = get_csum(csum, coff, b, s, d);
            val = (ce - cs) / (float)(e - s);
        }
        acc += score[b * P_ + p] * val;
    }
    video_seg[b * D_ + d] = acc;
}

// build preA [16, 2304] = [vseg | tseg | q]
__global__ void prea_kernel(const float* __restrict__ vseg,
                            const float* __restrict__ tseg,
                            const bf16* __restrict__ tout,  // q rows at 768..783
                            bf16* __restrict__ preA) {
    int b = blockIdx.x, d = threadIdx.x;
    preA[(size_t)b * 2304 + d] = __float2bfloat16_rn(vseg[b * D_ + d]);
    preA[(size_t)b * 2304 + D_ + d] = __float2bfloat16_rn(tseg[b * D_ + d]);
    preA[(size_t)b * 2304 + 2 * D_ + d] = tout[(size_t)(768 + b) * D_ + d];
}

__global__ void hseq_kernel(const bf16* __restrict__ xall,
                            const int* __restrict__ label,
                            const float* __restrict__ state0,
                            bf16* __restrict__ hseq) {
    int sb = blockIdx.x;          // s*B + b
    int s = sb / B_, b = sb % B_;
    int d = threadIdx.x;
    bf16 v;
    if (s == 0) {
        v = __float2bfloat16_rn(state0[d]);
    } else {
        int lab = label[b * S_ + (s - 1)];
        v = xall[(size_t)((b * S_ + (s - 1)) * A_ + lab) * DS_ + d];
    }
    hseq[(size_t)sb * DS_ + d] = v;
}

__global__ void gru_kernel(const float* __restrict__ gi,
                           const float* __restrict__ gh,
                           const bf16* __restrict__ hseq,
                           bf16* __restrict__ hnew) {
    int r = blockIdx.x;  // (b*S+s)*A+a
    int d = threadIdx.x;
    int bs = r / A_;
    int b = bs / S_, s = bs % S_;
    int sb = s * B_ + b;
    size_t gbase = (size_t)r * (3 * DS_);
    size_t hbase = (size_t)sb * (3 * DS_);
    float ir = gi[gbase + d];
    float iz = gi[gbase + DS_ + d];
    float in = gi[gbase + 2 * DS_ + d];
    float hr = gh[hbase + d];
    float hz = gh[hbase + DS_ + d];
    float hn = gh[hbase + 2 * DS_ + d];
    float h = __bfloat162float(hseq[(size_t)sb * DS_ + d]);
    float rg = 1.f / (1.f + expf(-(ir + hr)));
    float z = 1.f / (1.f + expf(-(iz + hz)));
    float n = tanhf(in + rg * hn);
    hnew[(size_t)r * DS_ + d] = __float2bfloat16_rn((1.f - z) * n + z * h);
}

__global__ void logits_kernel(const float* __restrict__ qh,
                              const float* __restrict__ wq2,
                              const float* __restrict__ bq2,
                              float* __restrict__ logits) {
    int warp = (blockIdx.x * blockDim.x + threadIdx.x) >> 5;
    int lane = threadIdx.x & 31;
    if (warp >= NROWS) return;
    float sum = 0.f;
    for (int d = lane; d < DS_; d += 32)
        sum += qh[(size_t)warp * DS_ + d] * wq2[d];
#pragma unroll
    for (int o = 16; o; o >>= 1) sum += __shfl_down_sync(0xffffffffu, sum, o);
    if (lane == 0) logits[warp] = sum + bq2[0];
}

__global__ void loss_kernel(const float* __restrict__ logits,
                            const int* __restrict__ label,
                            float* __restrict__ out) {
    __shared__ float sh[S_ * B_];
    int t = threadIdx.x;  // 0..191
    int b = t / S_, s = t % S_;
    const float* l = &logits[(size_t)(b * S_ + s) * A_];
    float mx = -1e30f;
    for (int a = 0; a < A_; a++) mx = fmaxf(mx, l[a]);
    float sum = 0.f;
    for (int a = 0; a < A_; a++) sum += expf(l[a] - mx);
    float lse = mx + logf(sum);
    int lab = label[b * S_ + s];
    sh[t] = lse - l[lab];
    __syncthreads();
    if (t == 0) {
        float tot = 0.f;
        for (int i = 0; i < S_ * B_; i++) tot += sh[i];
        out[0] = tot / (float)(S_ * B_);
    }
}

// ---------------- launch ------------------------------------------------------
static inline void cvt(const float* in, bf16* out, int n) {
    cvt32_kernel<<<(n / 4 + 255) / 256, 256>>>(in, out, n);
}

template <typename OT>
static inline void run_gemm(const bf16* A, const bf16* W, const float* bias,
                            OT* C, int M, int N, int K, int act, int ldc = 0) {
    if (ldc == 0) ldc = N;
    dim3 grid(N / 128, (M + 127) / 128);
    if (act == 0) {
        cudaFuncSetAttribute(hgemm<0, OT>,
                             cudaFuncAttributeMaxDynamicSharedMemorySize, TG_SMEM);
        hgemm<0, OT><<<grid, 256, TG_SMEM>>>(A, W, bias, C, M, N, K, ldc);
    } else if (act == 1) {
        cudaFuncSetAttribute(hgemm<1, OT>,
                             cudaFuncAttributeMaxDynamicSharedMemorySize, TG_SMEM);
        hgemm<1, OT><<<grid, 256, TG_SMEM>>>(A, W, bias, C, M, N, K, ldc);
    } else {
        cudaFuncSetAttribute(hgemm<2, OT>,
                             cudaFuncAttributeMaxDynamicSharedMemorySize, TG_SMEM);
        hgemm<2, OT><<<grid, 256, TG_SMEM>>>(A, W, bias, C, M, N, K, ldc);
    }
}

extern "C" void kernel_launch(void* const* d_in, const int* in_sizes, int n_in,
                              void* d_out, int out_size) {
    const float* video = (const float*)d_in[0];
    const float* para = (const float*)d_in[1];
    const float* question = (const float*)d_in[2];
    const float* a_texts = (const float*)d_in[3];
    const float* a_buttons = (const float*)d_in[4];
    const float* paras_score = (const float*)d_in[5];
    const int* starts = (const int*)d_in[6];
    const int* ends = (const int*)d_in[7];
    const int* label = (const int*)d_in[8];
    const float* wv1 = (const float*)d_in[9];
    const float* bv1 = (const float*)d_in[10];
    const float* wv2 = (const float*)d_in[11];
    const float* bv2 = (const float*)d_in[12];
    const float* wt1 = (const float*)d_in[13];
    const float* bt1 = (const float*)d_in[14];
    const float* wt2 = (const float*)d_in[15];
    const float* bt2 = (const float*)d_in[16];
    const float* wp1 = (const float*)d_in[17];
    const float* bp1 = (const float*)d_in[18];
    const float* wp2 = (const float*)d_in[19];
    const float* bp2 = (const float*)d_in[20];
    const float* w_ih = (const float*)d_in[21];
    const float* b_ih = (const float*)d_in[22];
    const float* w_hh = (const float*)d_in[23];
    const float* b_hh = (const float*)d_in[24];
    const float* wq1 = (const float*)d_in[25];
    const float* bq1 = (const float*)d_in[26];
    const float* wq2 = (const float*)d_in[27];
    const float* bq2 = (const float*)d_in[28];
    const float* state0 = (const float*)d_in[29];
    float* out = (float*)d_out;

    float *p_vv, *p_csum, *p_chs, *p_cho, *p_score, *p_tseg, *p_vseg, *p_pre,
        *p_gi, *p_gh, *p_qh, *p_logits;
    cudaGetSymbolAddress((void**)&p_vv, g_vv);
    cudaGetSymbolAddress((void**)&p_csum, g_csum);
    cudaGetSymbolAddress((void**)&p_chs, g_chunksum);
    cudaGetSymbolAddress((void**)&p_cho, g_chunkoff);
    cudaGetSymbolAddress((void**)&p_score, g_score);
    cudaGetSymbolAddress((void**)&p_tseg, g_textseg);
    cudaGetSymbolAddress((void**)&p_vseg, g_videoseg);
    cudaGetSymbolAddress((void**)&p_pre, g_pre);
    cudaGetSymbolAddress((void**)&p_gi, g_gi);
    cudaGetSymbolAddress((void**)&p_gh, g_gh);
    cudaGetSymbolAddress((void**)&p_qh, g_qh);
    cudaGetSymbolAddress((void**)&p_logits, g_logits);

    bf16 *q_video, *q_tin, *q_atx, *q_abt;
    bf16 *qw_v1, *qw_v2, *qw_t1, *qw_t2, *qw_p1, *qw_p2, *qw_ih, *qw_hh, *qw_q1;
    bf16 *q_h1, *q_tout, *q_comb, *q_preA, *q_xall, *q_hseq, *q_hnew;
    cudaGetSymbolAddress((void**)&q_video, c_video);
    cudaGetSymbolAddress((void**)&q_tin, c_tin);
    cudaGetSymbolAddress((void**)&q_atx, c_atx);
    cudaGetSymbolAddress((void**)&q_abt, c_abt);
    cudaGetSymbolAddress((void**)&qw_v1, b_wv1);
    cudaGetSymbolAddress((void**)&qw_v2, b_wv2);
    cudaGetSymbolAddress((void**)&qw_t1, b_wt1);
    cudaGetSymbolAddress((void**)&qw_t2, b_wt2);
    cudaGetSymbolAddress((void**)&qw_p1, b_wp1);
    cudaGetSymbolAddress((void**)&qw_p2, b_wp2);
    cudaGetSymbolAddress((void**)&qw_ih, b_wih);
    cudaGetSymbolAddress((void**)&qw_hh, b_whh);
    cudaGetSymbolAddress((void**)&qw_q1, b_wq1);
    cudaGetSymbolAddress((void**)&q_h1, b_h1);
    cudaGetSymbolAddress((void**)&q_tout, b_tout);
    cudaGetSymbolAddress((void**)&q_comb, b_comb);
    cudaGetSymbolAddress((void**)&q_preA, b_preA);
    cudaGetSymbolAddress((void**)&q_xall, b_xall);
    cudaGetSymbolAddress((void**)&q_hseq, b_hseq);
    cudaGetSymbolAddress((void**)&q_hnew, b_hnew);

    // 0. fp32 -> bf16 conversions (inputs + weights)
    cvt(video, q_video, B_ * T_ * D_);
    cvt(para, q_tin, B_ * P_ * D_);                  // rows 0..767
    cvt(question, q_tin + 768 * D_, B_ * D_);        // rows 768..783
    cvt(a_texts, q_atx, NROWS * D_);
    cvt(a_buttons, q_abt, NROWS * D_);
    cvt(wv1, qw_v1, D_ * D_);
    cvt(wv2, qw_v2, D_ * D_);
    cvt(wt1, qw_t1, D_ * D_);
    cvt(wt2, qw_t2, D_ * D_);
    cvt(wp1, qw_p1, 4 * D_ * 4 * D_);
    cvt(wp2, qw_p2, 4 * D_ * DS_);
    cvt(w_ih, qw_ih, DS_ * 3 * DS_);
    cvt(w_hh, qw_hh, DS_ * 3 * DS_);
    cvt(wq1, qw_q1, DS_ * DS_);

    // 1. softmax over paragraph scores
    softmax_paras_kernel<<<1, 32>>>(paras_score, p_score);

    // 2. batched text MLP for [para | question] -> tout; weighted sum -> tseg
    run_gemm(q_tin, qw_t1, bt1, q_h1, 784, D_, D_, 1);
    run_gemm(q_h1, qw_t2, bt2, q_tout, 784, D_, D_, 0);
    weighted_sum_kernel<<<B_, D_>>>(p_score, q_tout, p_tseg);

    // 3. video MLP (video weights) -> vv (fp32 for prefix sums)
    run_gemm(q_video, qw_v1, bv1, q_h1, B_ * T_, D_, D_, 1);
    run_gemm(q_h1, qw_v2, bv2, p_vv, B_ * T_, D_, D_, 0);

    // 4. chunked prefix sums + segment means -> video_seg
    csum_phase1<<<B_ * NCHUNK, D_>>>(p_vv, p_csum, p_chs);
    csum_phase2<<<B_, D_>>>(p_chs, p_cho);
    seg_kernel<<<B_, D_>>>(p_vv, p_csum, p_cho, p_score, starts, ends, p_vseg);

    // 5. answer MLPs -> combined [at | ab] buffer (ldc = 1536)
    run_gemm(q_atx, qw_t1, bt1, q_h1, NROWS, D_, D_, 1);
    run_gemm(q_h1, qw_t2, bt2, q_comb, NROWS, D_, D_, 0, 1536);
    run_gemm(q_abt, qw_v1, bv1, q_h1, NROWS, D_, D_, 1);
    run_gemm(q_h1, qw_v2, bv2, q_comb + D_, NROWS, D_, D_, 0, 1536);

    // 6. fused row bias: preA = [vseg|tseg|q]; pre = preA @ wp1[0:2304] + bp1
    prea_kernel<<<B_, D_>>>(p_vseg, p_tseg, q_tout, q_preA);
    run_gemm(q_preA, qw_p1, bp1, p_pre, B_, 4 * D_, 3 * D_, 0);

    // 7. fusion MLP: layer1 = relu(comb @ wp1[2304:4608] + pre[row/288]) -> h1
    run_gemm(q_comb, qw_p1 + (size_t)(2 * D_) * (4 * D_), p_pre, q_h1,
             NROWS, 4 * D_, 2 * D_, 2);
    run_gemm(q_h1, qw_p2, bp2, q_xall, NROWS, DS_, 4 * D_, 0);

    // 8. teacher-forced hidden states + GRU gates
    hseq_kernel<<<S_ * B_, DS_>>>(q_xall, label, state0, q_hseq);
    run_gemm(q_xall, qw_ih, b_ih, p_gi, NROWS, 3 * DS_, DS_, 0);
    run_gemm(q_hseq, qw_hh, b_hh, p_gh, S_ * B_, 3 * DS_, DS_, 0);
    gru_kernel<<<NROWS, DS_>>>(p_gi, p_gh, q_hseq, q_hnew);

    // 9. logits MLP + loss
    run_gemm(q_hnew, qw_q1, bq1, p_qh, NROWS, DS_, DS_, 1);
    logits_kernel<<<(NROWS * 32 + 255) / 256, 256>>>(p_qh, wq2, bq2, p_logits);
    loss_kernel<<<1, S_ * B_>>>(p_logits, label, out);
}

// round 7
// speedup vs baseline: 1.3474x; 1.0714x over previous
#include <cuda_runtime.h>
#include <cuda_bf16.h>
#include <cstdint>
#include <cstddef>

typedef __nv_bfloat16 bf16;

#define B_ 16
#define T_ 1024
#define P_ 48
#define S_ 12
#define A_ 24
#define D_ 768
#define DS_ 768
#define NROWS 4608   /* B*S*A */
#define SA_ 288      /* S*A rows per batch element */
#define CHUNK 64
#define NCHUNK 16    /* T/CHUNK */

#define TXT_ROWS 5392   /* 768 para + 16 question + 4608 a_texts */
#define VID_ROWS 20992  /* 16384 video + 4608 a_buttons */

// ---------------- fp32 scratch ------------------------------------------------
__device__ float g_vv[12582912];     // video_v [B,T,D]
__device__ float g_csum[12595200];   // chunk-local prefix sums [B,T+1,D]
__device__ float g_chunksum[196608]; // [B,NCHUNK,D]
__device__ float g_chunkoff[196608];
__device__ float g_score[B_ * P_];
__device__ float g_textseg[B_ * D_];
__device__ float g_videoseg[B_ * D_];
__device__ float g_pre[B_ * 3072];   // [16, 3072] fused row-bias (incl bp1)
__device__ float g_gi[10616832];     // [NROWS, 3*DS]
__device__ float g_gh[442368];       // [S*B, 3*DS]
__device__ float g_qh[3538944];      // [NROWS, DS]
__device__ float g_logits[NROWS];

// ---------------- bf16 scratch --------------------------------------------------
__device__ bf16 c_tin[4141056];      // [para(768) | question(16) | atx(4608)] x768
__device__ bf16 c_vin[16121856];     // [video(16384) | abt(4608)] x 768
__device__ bf16 b_wv1[589824], b_wv2[589824], b_wt1[589824], b_wt2[589824];
__device__ bf16 b_wp1[9437184], b_wp2[2359296];
__device__ bf16 b_wih[1769472], b_whh[1769472], b_wq1[589824];
__device__ bf16 b_h1[16121856];      // hidden scratch (max 20992*768)
__device__ bf16 b_tout[602112];      // [784, 768] text-MLP out (parat | q)
__device__ bf16 b_comb[7077888];     // [NROWS, 1536] = [at | ab]
__device__ bf16 b_preA[B_ * 2304];   // [16, 2304] = [vseg | tseg | q]
__device__ bf16 b_xall[3538944];
__device__ bf16 b_hseq[147456];
__device__ bf16 b_hnew[3538944];

// ============================================================================
// bf16 tensor-core GEMM: C = epi(A[M,K]bf16 @ W[K,N]bf16)
// ACT: 0 = +bias[N], 1 = relu(+bias[N]), 2 = relu(+bias[(r/288)*N + n])
// N multiple of 128, K multiple of 64, M arbitrary. ldc = C row stride.
// ============================================================================
#define BKH 64
#define SAK 72
#define SWN 136
#define ASZ (128 * SAK)
#define WSZ (BKH * SWN)
#define TG_SMEM ((2 * ASZ + 2 * WSZ) * 2)  /* 71680 bytes */

__device__ __forceinline__ void cp16(uint32_t dst_smem, const void* src, int sz) {
    asm volatile("cp.async.cg.shared.global [%0], [%1], 16, %2;\n" ::"r"(dst_smem),
                 "l"(src), "r"(sz));
}

__device__ __forceinline__ void ldsm4(uint32_t r[4], uint32_t addr) {
    asm volatile("ldmatrix.sync.aligned.m8n8.x4.shared.b16 {%0,%1,%2,%3},[%4];"
                 : "=r"(r[0]), "=r"(r[1]), "=r"(r[2]), "=r"(r[3])
                 : "r"(addr));
}

__device__ __forceinline__ void ldsm4t(uint32_t r[4], uint32_t addr) {
    asm volatile("ldmatrix.sync.aligned.m8n8.x4.trans.shared.b16 {%0,%1,%2,%3},[%4];"
                 : "=r"(r[0]), "=r"(r[1]), "=r"(r[2]), "=r"(r[3])
                 : "r"(addr));
}

__device__ __forceinline__ void mma_bf16(float c[4], const uint32_t a[4],
                                         const uint32_t b[2]) {
    asm volatile(
        "mma.sync.aligned.m16n8k16.row.col.f32.bf16.bf16.f32 "
        "{%0,%1,%2,%3},{%4,%5,%6,%7},{%8,%9},{%0,%1,%2,%3};"
        : "+f"(c[0]), "+f"(c[1]), "+f"(c[2]), "+f"(c[3])
        : "r"(a[0]), "r"(a[1]), "r"(a[2]), "r"(a[3]), "r"(b[0]), "r"(b[1]));
}

__device__ __forceinline__ void store2(float* C, size_t off, float x, float y) {
    *reinterpret_cast<float2*>(C + off) = make_float2(x, y);
}
__device__ __forceinline__ void store2(bf16* C, size_t off, float x, float y) {
    *reinterpret_cast<__nv_bfloat162*>(C + off) =
        __float22bfloat162_rn(make_float2(x, y));
}

template <int ACT, typename OT>
__global__ __launch_bounds__(256) void hgemm(const bf16* __restrict__ A,
                                             const bf16* __restrict__ W,
                                             const float* __restrict__ bias,
                                             OT* __restrict__ C,
                                             int M, int N, int K, int ldc) {
    extern __shared__ bf16 smh[];
    bf16* As = smh;
    bf16* Ws = smh + 2 * ASZ;

    const int tid = threadIdx.x;
    const int lane = tid & 31;
    const int warp = tid >> 5;
    const int warpM = (warp >> 2) * 64;
    const int warpN = (warp & 3) * 32;
    const int rowBase = blockIdx.y * 128;
    const int colBase = blockIdx.x * 128;
    const int KT = K / BKH;

    float acc[4][4][4];
#pragma unroll
    for (int i = 0; i < 4; i++)
#pragma unroll
        for (int j = 0; j < 4; j++)
#pragma unroll
            for (int k = 0; k < 4; k++) acc[i][j][k] = 0.f;

    auto loadTile = [&](int kt, int buf) {
        bf16* ad = As + buf * ASZ;
#pragma unroll
        for (int i = 0; i < 4; i++) {
            int idx = tid + i * 256;
            int row = idx >> 3, oct = idx & 7;
            int grow = rowBase + row;
            int crow = grow < M ? grow : 0;
            const bf16* src = A + (size_t)crow * K + kt * BKH + oct * 8;
            uint32_t d = (uint32_t)__cvta_generic_to_shared(ad + row * SAK + oct * 8);
            cp16(d, src, grow < M ? 16 : 0);
        }
        bf16* wd = Ws + buf * WSZ;
#pragma unroll
        for (int i = 0; i < 4; i++) {
            int idx = tid + i * 256;
            int row = idx >> 4, oct = idx & 15;
            const bf16* src = W + (size_t)(kt * BKH + row) * N + colBase + oct * 8;
            uint32_t d = (uint32_t)__cvta_generic_to_shared(wd + row * SWN + oct * 8);
            cp16(d, src, 16);
        }
    };

    loadTile(0, 0);
    asm volatile("cp.async.commit_group;\n");

    for (int kt = 0; kt < KT; kt++) {
        const int buf = kt & 1;
        if (kt + 1 < KT) {
            loadTile(kt + 1, buf ^ 1);
            asm volatile("cp.async.commit_group;\n");
            asm volatile("cp.async.wait_group 1;\n");
        } else {
            asm volatile("cp.async.wait_group 0;\n");
        }
        __syncthreads();

        const bf16* a_s = As + buf * ASZ;
        const bf16* w_s = Ws + buf * WSZ;

#pragma unroll
        for (int ks = 0; ks < BKH / 16; ks++) {
            const int k0 = ks * 16;
            uint32_t af[4][4], bfr[4][2];
#pragma unroll
            for (int mi = 0; mi < 4; mi++) {
                uint32_t ad = (uint32_t)__cvta_generic_to_shared(
                    a_s + (size_t)(warpM + mi * 16 + (lane & 15)) * SAK + k0 +
                    ((lane >> 4) * 8));
                ldsm4(af[mi], ad);
            }
#pragma unroll
            for (int nb = 0; nb < 2; nb++) {
                uint32_t tmp[4];
                uint32_t wdaddr = (uint32_t)__cvta_generic_to_shared(
                    w_s + (size_t)(k0 + (lane & 15)) * SWN + warpN + nb * 16 +
                    ((lane >> 4) * 8));
                ldsm4t(tmp, wdaddr);
                bfr[2 * nb][0] = tmp[0];
                bfr[2 * nb][1] = tmp[1];
                bfr[2 * nb + 1][0] = tmp[2];
                bfr[2 * nb + 1][1] = tmp[3];
            }
#pragma unroll
            for (int mi = 0; mi < 4; mi++)
#pragma unroll
                for (int ni = 0; ni < 4; ni++) mma_bf16(acc[mi][ni], af[mi], bfr[ni]);
        }
        __syncthreads();
    }

#pragma unroll
    for (int mi = 0; mi < 4; mi++) {
        const int r0 = rowBase + warpM + mi * 16 + (lane >> 2);
        const float* br0;
        const float* br8;
        if (ACT == 2) {
            int g0 = r0 / SA_;
            int g8 = (r0 + 8) / SA_;
            if (g0 > B_ - 1) g0 = B_ - 1;
            if (g8 > B_ - 1) g8 = B_ - 1;
            br0 = bias + (size_t)g0 * N;
            br8 = bias + (size_t)g8 * N;
        } else {
            br0 = bias;
            br8 = bias;
        }
#pragma unroll
        for (int ni = 0; ni < 4; ni++) {
            const int c = colBase + warpN + ni * 8 + 2 * (lane & 3);
            float v0 = acc[mi][ni][0] + br0[c];
            float v1 = acc[mi][ni][1] + br0[c + 1];
            float v2 = acc[mi][ni][2] + br8[c];
            float v3 = acc[mi][ni][3] + br8[c + 1];
            if (ACT >= 1) {
                v0 = fmaxf(v0, 0.f); v1 = fmaxf(v1, 0.f);
                v2 = fmaxf(v2, 0.f); v3 = fmaxf(v3, 0.f);
            }
            if (r0 < M) store2(C, (size_t)r0 * ldc + c, v0, v1);
            if (r0 + 8 < M) store2(C, (size_t)(r0 + 8) * ldc + c, v2, v3);
        }
    }
}

// ---------------- fused multi-segment fp32 -> bf16 conversion ------------------
#define NSEG 14
struct CvtSegs {
    const float* src[NSEG];
    bf16* dst[NSEG];
    long long off[NSEG + 1];  // cumulative element offsets
};

__global__ void cvt_multi_kernel(CvtSegs s) {
    long long i4 = ((long long)blockIdx.x * blockDim.x + threadIdx.x) * 4;
    if (i4 >= s.off[NSEG]) return;
    int seg = 0;
#pragma unroll
    for (int k = 1; k < NSEG; k++)
        if (i4 >= s.off[k]) seg = k;
    long long local = i4 - s.off[seg];
    float4 v = *reinterpret_cast<const float4*>(s.src[seg] + local);
    bf16* o = s.dst[seg] + local;
    *reinterpret_cast<__nv_bfloat162*>(o) =
        __float22bfloat162_rn(make_float2(v.x, v.y));
    *reinterpret_cast<__nv_bfloat162*>(o + 2) =
        __float22bfloat162_rn(make_float2(v.z, v.w));
}

// ---------------- small kernels ----------------------------------------------
__global__ void softmax_paras_kernel(const float* __restrict__ ps,
                                     float* __restrict__ score) {
    int b = threadIdx.x;
    if (b >= B_) return;
    float mx = -1e30f;
    for (int p = 0; p < P_; p++) mx = fmaxf(mx, ps[b * P_ + p]);
    float sum = 0.f;
    for (int p = 0; p < P_; p++) sum += expf(ps[b * P_ + p] - mx);
    float inv = 1.f / sum;
    for (int p = 0; p < P_; p++) score[b * P_ + p] = expf(ps[b * P_ + p] - mx) * inv;
}

__global__ void weighted_sum_kernel(const float* __restrict__ score,
                                    const bf16* __restrict__ x,   // [B,P,D]
                                    float* __restrict__ out) {    // [B,D]
    int b = blockIdx.x, d = threadIdx.x;
    float acc = 0.f;
    for (int p = 0; p < P_; p++)
        acc += score[b * P_ + p] *
               __bfloat162float(x[((size_t)(b * P_ + p)) * D_ + d]);
    out[b * D_ + d] = acc;
}

__global__ void csum_phase1(const float* __restrict__ vv,
                            float* __restrict__ csum,
                            float* __restrict__ chunksum) {
    int b = blockIdx.x / NCHUNK, c = blockIdx.x % NCHUNK;
    int d = threadIdx.x;
    float run = 0.f;
    int tbase = c * CHUNK;
    for (int i = 0; i < CHUNK; i++) {
        run += vv[((size_t)b * T_ + tbase + i) * D_ + d];
        csum[((size_t)b * (T_ + 1) + tbase + i + 1) * D_ + d] = run;
    }
    chunksum[(b * NCHUNK + c) * D_ + d] = run;
}

__global__ void csum_phase2(const float* __restrict__ chunksum,
                            float* __restrict__ chunkoff) {
    int b = blockIdx.x, d = threadIdx.x;
    float run = 0.f;
    for (int c = 0; c < NCHUNK; c++) {
        chunkoff[(b * NCHUNK + c) * D_ + d] = run;
        run += chunksum[(b * NCHUNK + c) * D_ + d];
    }
}

__device__ __forceinline__ float get_csum(const float* csum, const float* coff,
                                          int b, int t, int d) {
    if (t == 0) return 0.f;
    int c = (t - 1) >> 6;  // CHUNK=64
    return csum[((size_t)b * (T_ + 1) + t) * D_ + d] +
           coff[(b * NCHUNK + c) * D_ + d];
}

__global__ void seg_kernel(const float* __restrict__ vv,
                           const float* __restrict__ csum,
                           const float* __restrict__ coff,
                           const float* __restrict__ score,
                           const int* __restrict__ starts,
                           const int* __restrict__ ends,
                           float* __restrict__ video_seg) {
    int b = blockIdx.x, d = threadIdx.x;
    float acc = 0.f;
    for (int p = 0; p < P_; p++) {
        int s = starts[b * P_ + p], e = ends[b * P_ + p];
        float val;
        if (s >= e) {
            val = vv[((size_t)b * T_ + s) * D_ + d];
        } else {
            float ce = get_csum(csum, coff, b, e, d);
            float cs = get_csum(csum, coff, b, s, d);
            val = (ce - cs) / (float)(e - s);
        }
        acc += score[b * P_ + p] * val;
    }
    video_seg[b * D_ + d] = acc;
}

// build preA [16, 2304] = [vseg | tseg | q]
__global__ void prea_kernel(const float* __restrict__ vseg,
                            const float* __restrict__ tseg,
                            const bf16* __restrict__ tout,  // q rows at 768..783
                            bf16* __restrict__ preA) {
    int b = blockIdx.x, d = threadIdx.x;
    preA[(size_t)b * 2304 + d] = __float2bfloat16_rn(vseg[b * D_ + d]);
    preA[(size_t)b * 2304 + D_ + d] = __float2bfloat16_rn(tseg[b * D_ + d]);
    preA[(size_t)b * 2304 + 2 * D_ + d] = tout[(size_t)(768 + b) * D_ + d];
}

__global__ void hseq_kernel(const bf16* __restrict__ xall,
                            const int* __restrict__ label,
                            const float* __restrict__ state0,
                            bf16* __restrict__ hseq) {
    int sb = blockIdx.x;          // s*B + b
    int s = sb / B_, b = sb % B_;
    int d = threadIdx.x;
    bf16 v;
    if (s == 0) {
        v = __float2bfloat16_rn(state0[d]);
    } else {
        int lab = label[b * S_ + (s - 1)];
        v = xall[(size_t)((b * S_ + (s - 1)) * A_ + lab) * DS_ + d];
    }
    hseq[(size_t)sb * DS_ + d] = v;
}

__global__ void gru_kernel(const float* __restrict__ gi,
                           const float* __restrict__ gh,
                           const bf16* __restrict__ hseq,
                           bf16* __restrict__ hnew) {
    int r = blockIdx.x;  // (b*S+s)*A+a
    int d = threadIdx.x;
    int bs = r / A_;
    int b = bs / S_, s = bs % S_;
    int sb = s * B_ + b;
    size_t gbase = (size_t)r * (3 * DS_);
    size_t hbase = (size_t)sb * (3 * DS_);
    float ir = gi[gbase + d];
    float iz = gi[gbase + DS_ + d];
    float in = gi[gbase + 2 * DS_ + d];
    float hr = gh[hbase + d];
    float hz = gh[hbase + DS_ + d];
    float hn = gh[hbase + 2 * DS_ + d];
    float h = __bfloat162float(hseq[(size_t)sb * DS_ + d]);
    float rg = 1.f / (1.f + expf(-(ir + hr)));
    float z = 1.f / (1.f + expf(-(iz + hz)));
    float n = tanhf(in + rg * hn);
    hnew[(size_t)r * DS_ + d] = __float2bfloat16_rn((1.f - z) * n + z * h);
}

__global__ void logits_kernel(const float* __restrict__ qh,
                              const float* __restrict__ wq2,
                              const float* __restrict__ bq2,
                              float* __restrict__ logits) {
    int warp = (blockIdx.x * blockDim.x + threadIdx.x) >> 5;
    int lane = threadIdx.x & 31;
    if (warp >= NROWS) return;
    float sum = 0.f;
    for (int d = lane; d < DS_; d += 32)
        sum += qh[(size_t)warp * DS_ + d] * wq2[d];
#pragma unroll
    for (int o = 16; o; o >>= 1) sum += __shfl_down_sync(0xffffffffu, sum, o);
    if (lane == 0) logits[warp] = sum + bq2[0];
}

__global__ void loss_kernel(const float* __restrict__ logits,
                            const int* __restrict__ label,
                            float* __restrict__ out) {
    __shared__ float sh[S_ * B_];
    int t = threadIdx.x;  // 0..191
    int b = t / S_, s = t % S_;
    const float* l = &logits[(size_t)(b * S_ + s) * A_];
    float mx = -1e30f;
    for (int a = 0; a < A_; a++) mx = fmaxf(mx, l[a]);
    float sum = 0.f;
    for (int a = 0; a < A_; a++) sum += expf(l[a] - mx);
    float lse = mx + logf(sum);
    int lab = label[b * S_ + s];
    sh[t] = lse - l[lab];
    __syncthreads();
    if (t == 0) {
        float tot = 0.f;
        for (int i = 0; i < S_ * B_; i++) tot += sh[i];
        out[0] = tot / (float)(S_ * B_);
    }
}

// ---------------- launch ------------------------------------------------------
template <typename OT>
static inline void run_gemm(const bf16* A, const bf16* W, const float* bias,
                            OT* C, int M, int N, int K, int act, int ldc = 0) {
    if (ldc == 0) ldc = N;
    dim3 grid(N / 128, (M + 127) / 128);
    if (act == 0) {
        cudaFuncSetAttribute(hgemm<0, OT>,
                             cudaFuncAttributeMaxDynamicSharedMemorySize, TG_SMEM);
        hgemm<0, OT><<<grid, 256, TG_SMEM>>>(A, W, bias, C, M, N, K, ldc);
    } else if (act == 1) {
        cudaFuncSetAttribute(hgemm<1, OT>,
                             cudaFuncAttributeMaxDynamicSharedMemorySize, TG_SMEM);
        hgemm<1, OT><<<grid, 256, TG_SMEM>>>(A, W, bias, C, M, N, K, ldc);
    } else {
        cudaFuncSetAttribute(hgemm<2, OT>,
                             cudaFuncAttributeMaxDynamicSharedMemorySize, TG_SMEM);
        hgemm<2, OT><<<grid, 256, TG_SMEM>>>(A, W, bias, C, M, N, K, ldc);
    }
}

extern "C" void kernel_launch(void* const* d_in, const int* in_sizes, int n_in,
                              void* d_out, int out_size) {
    const float* video = (const float*)d_in[0];
    const float* para = (const float*)d_in[1];
    const float* question = (const float*)d_in[2];
    const float* a_texts = (const float*)d_in[3];
    const float* a_buttons = (const float*)d_in[4];
    const float* paras_score = (const float*)d_in[5];
    const int* starts = (const int*)d_in[6];
    const int* ends = (const int*)d_in[7];
    const int* label = (const int*)d_in[8];
    const float* wv1 = (const float*)d_in[9];
    const float* bv1 = (const float*)d_in[10];
    const float* wv2 = (const float*)d_in[11];
    const float* bv2 = (const float*)d_in[12];
    const float* wt1 = (const float*)d_in[13];
    const float* bt1 = (const float*)d_in[14];
    const float* wt2 = (const float*)d_in[15];
    const float* bt2 = (const float*)d_in[16];
    const float* wp1 = (const float*)d_in[17];
    const float* bp1 = (const float*)d_in[18];
    const float* wp2 = (const float*)d_in[19];
    const float* bp2 = (const float*)d_in[20];
    const float* w_ih = (const float*)d_in[21];
    const float* b_ih = (const float*)d_in[22];
    const float* w_hh = (const float*)d_in[23];
    const float* b_hh = (const float*)d_in[24];
    const float* wq1 = (const float*)d_in[25];
    const float* bq1 = (const float*)d_in[26];
    const float* wq2 = (const float*)d_in[27];
    const float* bq2 = (const float*)d_in[28];
    const float* state0 = (const float*)d_in[29];
    float* out = (float*)d_out;

    float *p_vv, *p_csum, *p_chs, *p_cho, *p_score, *p_tseg, *p_vseg, *p_pre,
        *p_gi, *p_gh, *p_qh, *p_logits;
    cudaGetSymbolAddress((void**)&p_vv, g_vv);
    cudaGetSymbolAddress((void**)&p_csum, g_csum);
    cudaGetSymbolAddress((void**)&p_chs, g_chunksum);
    cudaGetSymbolAddress((void**)&p_cho, g_chunkoff);
    cudaGetSymbolAddress((void**)&p_score, g_score);
    cudaGetSymbolAddress((void**)&p_tseg, g_textseg);
    cudaGetSymbolAddress((void**)&p_vseg, g_videoseg);
    cudaGetSymbolAddress((void**)&p_pre, g_pre);
    cudaGetSymbolAddress((void**)&p_gi, g_gi);
    cudaGetSymbolAddress((void**)&p_gh, g_gh);
    cudaGetSymbolAddress((void**)&p_qh, g_qh);
    cudaGetSymbolAddress((void**)&p_logits, g_logits);

    bf16 *q_tin, *q_vin;
    bf16 *qw_v1, *qw_v2, *qw_t1, *qw_t2, *qw_p1, *qw_p2, *qw_ih, *qw_hh, *qw_q1;
    bf16 *q_h1, *q_tout, *q_comb, *q_preA, *q_xall, *q_hseq, *q_hnew;
    cudaGetSymbolAddress((void**)&q_tin, c_tin);
    cudaGetSymbolAddress((void**)&q_vin, c_vin);
    cudaGetSymbolAddress((void**)&qw_v1, b_wv1);
    cudaGetSymbolAddress((void**)&qw_v2, b_wv2);
    cudaGetSymbolAddress((void**)&qw_t1, b_wt1);
    cudaGetSymbolAddress((void**)&qw_t2, b_wt2);
    cudaGetSymbolAddress((void**)&qw_p1, b_wp1);
    cudaGetSymbolAddress((void**)&qw_p2, b_wp2);
    cudaGetSymbolAddress((void**)&qw_ih, b_wih);
    cudaGetSymbolAddress((void**)&qw_hh, b_whh);
    cudaGetSymbolAddress((void**)&qw_q1, b_wq1);
    cudaGetSymbolAddress((void**)&q_h1, b_h1);
    cudaGetSymbolAddress((void**)&q_tout, b_tout);
    cudaGetSymbolAddress((void**)&q_comb, b_comb);
    cudaGetSymbolAddress((void**)&q_preA, b_preA);
    cudaGetSymbolAddress((void**)&q_xall, b_xall);
    cudaGetSymbolAddress((void**)&q_hseq, b_hseq);
    cudaGetSymbolAddress((void**)&q_hnew, b_hnew);

    // 0. single fused fp32 -> bf16 conversion pass (inputs + weights)
    {
        CvtSegs cs;
        const float* srcs[NSEG] = {para, question, a_texts, video, a_buttons,
                                   wv1, wv2, wt1, wt2, wp1, wp2, w_ih, w_hh, wq1};
        bf16* dsts[NSEG] = {q_tin, q_tin + 768 * D_, q_tin + 784 * D_,
                            q_vin, q_vin + (size_t)16384 * D_,
                            qw_v1, qw_v2, qw_t1, qw_t2, qw_p1, qw_p2,
                            qw_ih, qw_hh, qw_q1};
        long long ns[NSEG] = {768 * D_, B_ * D_, NROWS * D_,
                              (long long)B_ * T_ * D_, (long long)NROWS * D_,
                              D_ * D_, D_ * D_, D_ * D_, D_ * D_,
                              (long long)4 * D_ * 4 * D_, (long long)4 * D_ * DS_,
                              (long long)DS_ * 3 * DS_, (long long)DS_ * 3 * DS_,
                              (long long)DS_ * DS_};
        long long acc = 0;
        for (int i = 0; i < NSEG; i++) {
            cs.src[i] = srcs[i];
            cs.dst[i] = dsts[i];
            cs.off[i] = acc;
            acc += ns[i];
        }
        cs.off[NSEG] = acc;
        long long nthreads = acc / 4;
        cvt_multi_kernel<<<(unsigned)((nthreads + 255) / 256), 256>>>(cs);
    }

    // 1. softmax over paragraph scores
    softmax_paras_kernel<<<1, 32>>>(paras_score, p_score);

    // 2. merged text MLP: [para | question | a_texts] through wt1/wt2
    run_gemm(q_tin, qw_t1, bt1, q_h1, TXT_ROWS, D_, D_, 1);
    run_gemm(q_h1, qw_t2, bt2, q_tout, 784, D_, D_, 0);                    // parat|q
    run_gemm(q_h1 + (size_t)784 * D_, qw_t2, bt2, q_comb, NROWS, D_, D_, 0,
             1536);                                                        // at
    weighted_sum_kernel<<<B_, D_>>>(p_score, q_tout, p_tseg);

    // 3. merged video MLP: [video | a_buttons] through wv1/wv2
    run_gemm(q_vin, qw_v1, bv1, q_h1, VID_ROWS, D_, D_, 1);
    run_gemm(q_h1, qw_v2, bv2, p_vv, B_ * T_, D_, D_, 0);                  // vv fp32
    run_gemm(q_h1 + (size_t)16384 * D_, qw_v2, bv2, q_comb + D_, NROWS, D_, D_,
             0, 1536);                                                     // ab

    // 4. chunked prefix sums + segment means -> video_seg
    csum_phase1<<<B_ * NCHUNK, D_>>>(p_vv, p_csum, p_chs);
    csum_phase2<<<B_, D_>>>(p_chs, p_cho);
    seg_kernel<<<B_, D_>>>(p_vv, p_csum, p_cho, p_score, starts, ends, p_vseg);

    // 5. fused row bias: preA = [vseg|tseg|q]; pre = preA @ wp1[0:2304] + bp1
    prea_kernel<<<B_, D_>>>(p_vseg, p_tseg, q_tout, q_preA);
    run_gemm(q_preA, qw_p1, bp1, p_pre, B_, 4 * D_, 3 * D_, 0);

    // 6. fusion MLP: layer1 = relu(comb @ wp1[2304:4608] + pre[row/288]) -> h1
    run_gemm(q_comb, qw_p1 + (size_t)(2 * D_) * (4 * D_), p_pre, q_h1,
             NROWS, 4 * D_, 2 * D_, 2);
    run_gemm(q_h1, qw_p2, bp2, q_xall, NROWS, DS_, 4 * D_, 0);

    // 7. teacher-forced hidden states + GRU gates
    hseq_kernel<<<S_ * B_, DS_>>>(q_xall, label, state0, q_hseq);
    run_gemm(q_xall, qw_ih, b_ih, p_gi, NROWS, 3 * DS_, DS_, 0);
    run_gemm(q_hseq, qw_hh, b_hh, p_gh, S_ * B_, 3 * DS_, DS_, 0);
    gru_kernel<<<NROWS, DS_>>>(p_gi, p_gh, q_hseq, q_hnew);

    // 8. logits MLP + loss
    run_gemm(q_hnew, qw_q1, bq1, p_qh, NROWS, DS_, DS_, 1);
    logits_kernel<<<(NROWS * 32 + 255) / 256, 256>>>(p_qh, wq2, bq2, p_logits);
    loss_kernel<<<1, S_ * B_>>>(p_logits, label, out);
}

// round 8
// speedup vs baseline: 1.5098x; 1.1205x over previous
#include <cuda_runtime.h>
#include <cuda_bf16.h>
#include <cstdint>
#include <cstddef>

typedef __nv_bfloat16 bf16;

#define B_ 16
#define T_ 1024
#define P_ 48
#define S_ 12
#define A_ 24
#define D_ 768
#define DS_ 768
#define NROWS 4608   /* B*S*A */
#define SA_ 288      /* S*A rows per batch element */

#define TXT_ROWS 5392   /* 768 para + 16 question + 4608 a_texts */
#define VID_ROWS 20992  /* 16384 video + 4608 a_buttons */

// ---------------- fp32 scratch ------------------------------------------------
__device__ float g_score[B_ * P_];
__device__ float g_wts[B_ * T_];       // per-(b,t) segment weights
__device__ float g_part[B_ * 8 * D_];  // partial weighted sums of video h1
__device__ float g_vseg[B_ * D_];      // video_seg fp32
__device__ float g_tq[32 * D_];        // [tseg(16) | q(16)] fp32
__device__ float g_pre[B_ * 3072];     // [16, 3072] fused row-bias (incl bp1)
__device__ float g_gi[10616832];       // [NROWS, 3*DS]
__device__ float g_gh[442368];         // [S*B, 3*DS]
__device__ float g_qh[3538944];        // [NROWS, DS]
__device__ float g_logits[NROWS];

// ---------------- bf16 scratch --------------------------------------------------
__device__ bf16 c_tin[4141056];      // [para(768)|question(16)|atx(4608)] x 768
__device__ bf16 c_vin[16121856];     // [video(16384)|abt(4608)] x 768
__device__ bf16 b_wv1[589824], b_wv2[589824], b_wt1[589824], b_wt2[589824];
__device__ bf16 b_wp1[9437184], b_wp2[2359296];
__device__ bf16 b_wih[1769472], b_whh[1769472], b_wq1[589824];
__device__ bf16 b_h1t[4141056];      // text L1 hidden [5392, 768]
__device__ bf16 b_h1[16121856];      // video L1 hidden [20992,768]; reused by fusion
__device__ bf16 b_svid[B_ * D_];     // weighted-reduced video h1 (bf16)
__device__ bf16 b_stxt[32 * D_];     // [wsum_para(16) | q_h1(16)] (bf16)
__device__ bf16 b_comb[7077888];     // [NROWS, 1536] = [at | ab]
__device__ bf16 b_preA[B_ * 2304];   // [16, 2304] = [vseg | tseg | q]
__device__ bf16 b_xall[3538944];
__device__ bf16 b_hseq[147456];
__device__ bf16 b_hnew[3538944];

// ============================================================================
// bf16 tensor-core GEMM: C = epi(A[M,K]bf16 @ W[K,N]bf16)
// ACT: 0 = +bias[N], 1 = relu(+bias[N]), 2 = relu(+bias[(r/288)*N + n])
// N multiple of 128, K multiple of 64, M arbitrary. ldc = C row stride.
// ============================================================================
#define BKH 64
#define SAK 72
#define SWN 136
#define ASZ (128 * SAK)
#define WSZ (BKH * SWN)
#define TG_SMEM ((2 * ASZ + 2 * WSZ) * 2)  /* 71680 bytes */

__device__ __forceinline__ void cp16(uint32_t dst_smem, const void* src, int sz) {
    asm volatile("cp.async.cg.shared.global [%0], [%1], 16, %2;\n" ::"r"(dst_smem),
                 "l"(src), "r"(sz));
}

__device__ __forceinline__ void ldsm4(uint32_t r[4], uint32_t addr) {
    asm volatile("ldmatrix.sync.aligned.m8n8.x4.shared.b16 {%0,%1,%2,%3},[%4];"
                 : "=r"(r[0]), "=r"(r[1]), "=r"(r[2]), "=r"(r[3])
                 : "r"(addr));
}

__device__ __forceinline__ void ldsm4t(uint32_t r[4], uint32_t addr) {
    asm volatile("ldmatrix.sync.aligned.m8n8.x4.trans.shared.b16 {%0,%1,%2,%3},[%4];"
                 : "=r"(r[0]), "=r"(r[1]), "=r"(r[2]), "=r"(r[3])
                 : "r"(addr));
}

__device__ __forceinline__ void mma_bf16(float c[4], const uint32_t a[4],
                                         const uint32_t b[2]) {
    asm volatile(
        "mma.sync.aligned.m16n8k16.row.col.f32.bf16.bf16.f32 "
        "{%0,%1,%2,%3},{%4,%5,%6,%7},{%8,%9},{%0,%1,%2,%3};"
        : "+f"(c[0]), "+f"(c[1]), "+f"(c[2]), "+f"(c[3])
        : "r"(a[0]), "r"(a[1]), "r"(a[2]), "r"(a[3]), "r"(b[0]), "r"(b[1]));
}

__device__ __forceinline__ void store2(float* C, size_t off, float x, float y) {
    *reinterpret_cast<float2*>(C + off) = make_float2(x, y);
}
__device__ __forceinline__ void store2(bf16* C, size_t off, float x, float y) {
    *reinterpret_cast<__nv_bfloat162*>(C + off) =
        __float22bfloat162_rn(make_float2(x, y));
}

template <int ACT, typename OT>
__global__ __launch_bounds__(256) void hgemm(const bf16* __restrict__ A,
                                             const bf16* __restrict__ W,
                                             const float* __restrict__ bias,
                                             OT* __restrict__ C,
                                             int M, int N, int K, int ldc) {
    extern __shared__ bf16 smh[];
    bf16* As = smh;
    bf16* Ws = smh + 2 * ASZ;

    const int tid = threadIdx.x;
    const int lane = tid & 31;
    const int warp = tid >> 5;
    const int warpM = (warp >> 2) * 64;
    const int warpN = (warp & 3) * 32;
    const int rowBase = blockIdx.y * 128;
    const int colBase = blockIdx.x * 128;
    const int KT = K / BKH;

    float acc[4][4][4];
#pragma unroll
    for (int i = 0; i < 4; i++)
#pragma unroll
        for (int j = 0; j < 4; j++)
#pragma unroll
            for (int k = 0; k < 4; k++) acc[i][j][k] = 0.f;

    auto loadTile = [&](int kt, int buf) {
        bf16* ad = As + buf * ASZ;
#pragma unroll
        for (int i = 0; i < 4; i++) {
            int idx = tid + i * 256;
            int row = idx >> 3, oct = idx & 7;
            int grow = rowBase + row;
            int crow = grow < M ? grow : 0;
            const bf16* src = A + (size_t)crow * K + kt * BKH + oct * 8;
            uint32_t d = (uint32_t)__cvta_generic_to_shared(ad + row * SAK + oct * 8);
            cp16(d, src, grow < M ? 16 : 0);
        }
        bf16* wd = Ws + buf * WSZ;
#pragma unroll
        for (int i = 0; i < 4; i++) {
            int idx = tid + i * 256;
            int row = idx >> 4, oct = idx & 15;
            const bf16* src = W + (size_t)(kt * BKH + row) * N + colBase + oct * 8;
            uint32_t d = (uint32_t)__cvta_generic_to_shared(wd + row * SWN + oct * 8);
            cp16(d, src, 16);
        }
    };

    loadTile(0, 0);
    asm volatile("cp.async.commit_group;\n");

    for (int kt = 0; kt < KT; kt++) {
        const int buf = kt & 1;
        if (kt + 1 < KT) {
            loadTile(kt + 1, buf ^ 1);
            asm volatile("cp.async.commit_group;\n");
            asm volatile("cp.async.wait_group 1;\n");
        } else {
            asm volatile("cp.async.wait_group 0;\n");
        }
        __syncthreads();

        const bf16* a_s = As + buf * ASZ;
        const bf16* w_s = Ws + buf * WSZ;

#pragma unroll
        for (int ks = 0; ks < BKH / 16; ks++) {
            const int k0 = ks * 16;
            uint32_t af[4][4], bfr[4][2];
#pragma unroll
            for (int mi = 0; mi < 4; mi++) {
                uint32_t ad = (uint32_t)__cvta_generic_to_shared(
                    a_s + (size_t)(warpM + mi * 16 + (lane & 15)) * SAK + k0 +
                    ((lane >> 4) * 8));
                ldsm4(af[mi], ad);
            }
#pragma unroll
            for (int nb = 0; nb < 2; nb++) {
                uint32_t tmp[4];
                uint32_t wdaddr = (uint32_t)__cvta_generic_to_shared(
                    w_s + (size_t)(k0 + (lane & 15)) * SWN + warpN + nb * 16 +
                    ((lane >> 4) * 8));
                ldsm4t(tmp, wdaddr);
                bfr[2 * nb][0] = tmp[0];
                bfr[2 * nb][1] = tmp[1];
                bfr[2 * nb + 1][0] = tmp[2];
                bfr[2 * nb + 1][1] = tmp[3];
            }
#pragma unroll
            for (int mi = 0; mi < 4; mi++)
#pragma unroll
                for (int ni = 0; ni < 4; ni++) mma_bf16(acc[mi][ni], af[mi], bfr[ni]);
        }
        __syncthreads();
    }

#pragma unroll
    for (int mi = 0; mi < 4; mi++) {
        const int r0 = rowBase + warpM + mi * 16 + (lane >> 2);
        const float* br0;
        const float* br8;
        if (ACT == 2) {
            int g0 = r0 / SA_;
            int g8 = (r0 + 8) / SA_;
            if (g0 > B_ - 1) g0 = B_ - 1;
            if (g8 > B_ - 1) g8 = B_ - 1;
            br0 = bias + (size_t)g0 * N;
            br8 = bias + (size_t)g8 * N;
        } else {
            br0 = bias;
            br8 = bias;
        }
#pragma unroll
        for (int ni = 0; ni < 4; ni++) {
            const int c = colBase + warpN + ni * 8 + 2 * (lane & 3);
            float v0 = acc[mi][ni][0] + br0[c];
            float v1 = acc[mi][ni][1] + br0[c + 1];
            float v2 = acc[mi][ni][2] + br8[c];
            float v3 = acc[mi][ni][3] + br8[c + 1];
            if (ACT >= 1) {
                v0 = fmaxf(v0, 0.f); v1 = fmaxf(v1, 0.f);
                v2 = fmaxf(v2, 0.f); v3 = fmaxf(v3, 0.f);
            }
            if (r0 < M) store2(C, (size_t)r0 * ldc + c, v0, v1);
            if (r0 + 8 < M) store2(C, (size_t)(r0 + 8) * ldc + c, v2, v3);
        }
    }
}

// ---------------- fused multi-segment fp32 -> bf16 conversion ------------------
#define NSEG 14
struct CvtSegs {
    const float* src[NSEG];
    bf16* dst[NSEG];
    long long off[NSEG + 1];
};

__global__ void cvt_multi_kernel(CvtSegs s) {
    long long i4 = ((long long)blockIdx.x * blockDim.x + threadIdx.x) * 4;
    if (i4 >= s.off[NSEG]) return;
    int seg = 0;
#pragma unroll
    for (int k = 1; k < NSEG; k++)
        if (i4 >= s.off[k]) seg = k;
    long long local = i4 - s.off[seg];
    float4 v = *reinterpret_cast<const float4*>(s.src[seg] + local);
    bf16* o = s.dst[seg] + local;
    *reinterpret_cast<__nv_bfloat162*>(o) =
        __float22bfloat162_rn(make_float2(v.x, v.y));
    *reinterpret_cast<__nv_bfloat162*>(o + 2) =
        __float22bfloat162_rn(make_float2(v.z, v.w));
}

// ---------------- small kernels ----------------------------------------------
__global__ void softmax_paras_kernel(const float* __restrict__ ps,
                                     float* __restrict__ score) {
    int b = threadIdx.x;
    if (b >= B_) return;
    float mx = -1e30f;
    for (int p = 0; p < P_; p++) mx = fmaxf(mx, ps[b * P_ + p]);
    float sum = 0.f;
    for (int p = 0; p < P_; p++) sum += expf(ps[b * P_ + p] - mx);
    float inv = 1.f / sum;
    for (int p = 0; p < P_; p++) score[b * P_ + p] = expf(ps[b * P_ + p] - mx) * inv;
}

// per-(b,t) weights: w[b,t] = sum_p score * (1[s<=t<e]/(e-s)  or  1[t==s] if s>=e)
__global__ void wts_kernel(const float* __restrict__ score,
                           const int* __restrict__ starts,
                           const int* __restrict__ ends,
                           float* __restrict__ wts) {
    int b = blockIdx.x, t = threadIdx.x;
    float w = 0.f;
    for (int p = 0; p < P_; p++) {
        int s = starts[b * P_ + p], e = ends[b * P_ + p];
        float sc = score[b * P_ + p];
        if (s >= e) {
            if (t == s) w += sc;
        } else if (t >= s && t < e) {
            w += sc / (float)(e - s);
        }
    }
    wts[b * T_ + t] = w;
}

// partial weighted reduce over video h1: part[b][c][d] = sum_{t in chunk c} w*h1
__global__ void wred_kernel(const float* __restrict__ wts,
                            const bf16* __restrict__ h1v,
                            float* __restrict__ part) {
    int c = blockIdx.x, b = blockIdx.y, d = threadIdx.x;
    float acc = 0.f;
    int tbase = c * 128;
    for (int i = 0; i < 128; i++) {
        int t = tbase + i;
        acc += wts[b * T_ + t] *
               __bfloat162float(h1v[((size_t)b * T_ + t) * D_ + d]);
    }
    part[((size_t)b * 8 + c) * D_ + d] = acc;
}

// combine partials -> bf16 svid
__global__ void vcomb_kernel(const float* __restrict__ part,
                             bf16* __restrict__ svid) {
    int b = blockIdx.x, d = threadIdx.x;
    float acc = 0.f;
#pragma unroll
    for (int c = 0; c < 8; c++) acc += part[((size_t)b * 8 + c) * D_ + d];
    svid[b * D_ + d] = __float2bfloat16_rn(acc);
}

// stxt rows 0..15: score-weighted sum of para h1; rows 16..31: question h1 copy
__global__ void stxt_kernel(const float* __restrict__ score,
                            const bf16* __restrict__ h1t,
                            bf16* __restrict__ stxt) {
    int b = blockIdx.x, d = threadIdx.x;
    float acc = 0.f;
    for (int p = 0; p < P_; p++)
        acc += score[b * P_ + p] *
               __bfloat162float(h1t[((size_t)(b * P_ + p)) * D_ + d]);
    stxt[b * D_ + d] = __float2bfloat16_rn(acc);
    stxt[(16 + b) * D_ + d] = h1t[(size_t)(768 + b) * D_ + d];
}

// build preA [16, 2304] = [vseg | tseg | q]
__global__ void prea_kernel(const float* __restrict__ vseg,
                            const float* __restrict__ tq,
                            bf16* __restrict__ preA) {
    int b = blockIdx.x, d = threadIdx.x;
    preA[(size_t)b * 2304 + d] = __float2bfloat16_rn(vseg[b * D_ + d]);
    preA[(size_t)b * 2304 + D_ + d] = __float2bfloat16_rn(tq[b * D_ + d]);
    preA[(size_t)b * 2304 + 2 * D_ + d] =
        __float2bfloat16_rn(tq[(size_t)(16 + b) * D_ + d]);
}

__global__ void hseq_kernel(const bf16* __restrict__ xall,
                            const int* __restrict__ label,
                            const float* __restrict__ state0,
                            bf16* __restrict__ hseq) {
    int sb = blockIdx.x;          // s*B + b
    int s = sb / B_, b = sb % B_;
    int d = threadIdx.x;
    bf16 v;
    if (s == 0) {
        v = __float2bfloat16_rn(state0[d]);
    } else {
        int lab = label[b * S_ + (s - 1)];
        v = xall[(size_t)((b * S_ + (s - 1)) * A_ + lab) * DS_ + d];
    }
    hseq[(size_t)sb * DS_ + d] = v;
}

__global__ void gru_kernel(const float* __restrict__ gi,
                           const float* __restrict__ gh,
                           const bf16* __restrict__ hseq,
                           bf16* __restrict__ hnew) {
    int r = blockIdx.x;  // (b*S+s)*A+a
    int d = threadIdx.x;
    int bs = r / A_;
    int b = bs / S_, s = bs % S_;
    int sb = s * B_ + b;
    size_t gbase = (size_t)r * (3 * DS_);
    size_t hbase = (size_t)sb * (3 * DS_);
    float ir = gi[gbase + d];
    float iz = gi[gbase + DS_ + d];
    float in = gi[gbase + 2 * DS_ + d];
    float hr = gh[hbase + d];
    float hz = gh[hbase + DS_ + d];
    float hn = gh[hbase + 2 * DS_ + d];
    float h = __bfloat162float(hseq[(size_t)sb * DS_ + d]);
    float rg = 1.f / (1.f + expf(-(ir + hr)));
    float z = 1.f / (1.f + expf(-(iz + hz)));
    float n = tanhf(in + rg * hn);
    hnew[(size_t)r * DS_ + d] = __float2bfloat16_rn((1.f - z) * n + z * h);
}

__global__ void logits_kernel(const float* __restrict__ qh,
                              const float* __restrict__ wq2,
                              const float* __restrict__ bq2,
                              float* __restrict__ logits) {
    int warp = (blockIdx.x * blockDim.x + threadIdx.x) >> 5;
    int lane = threadIdx.x & 31;
    if (warp >= NROWS) return;
    float sum = 0.f;
    for (int d = lane; d < DS_; d += 32)
        sum += qh[(size_t)warp * DS_ + d] * wq2[d];
#pragma unroll
    for (int o = 16; o; o >>= 1) sum += __shfl_down_sync(0xffffffffu, sum, o);
    if (lane == 0) logits[warp] = sum + bq2[0];
}

__global__ void loss_kernel(const float* __restrict__ logits,
                            const int* __restrict__ label,
                            float* __restrict__ out) {
    __shared__ float sh[S_ * B_];
    int t = threadIdx.x;  // 0..191
    int b = t / S_, s = t % S_;
    const float* l = &logits[(size_t)(b * S_ + s) * A_];
    float mx = -1e30f;
    for (int a = 0; a < A_; a++) mx = fmaxf(mx, l[a]);
    float sum = 0.f;
    for (int a = 0; a < A_; a++) sum += expf(l[a] - mx);
    float lse = mx + logf(sum);
    int lab = label[b * S_ + s];
    sh[t] = lse - l[lab];
    __syncthreads();
    if (t == 0) {
        float tot = 0.f;
        for (int i = 0; i < S_ * B_; i++) tot += sh[i];
        out[0] = tot / (float)(S_ * B_);
    }
}

// ---------------- launch ------------------------------------------------------
template <typename OT>
static inline void run_gemm(const bf16* A, const bf16* W, const float* bias,
                            OT* C, int M, int N, int K, int act, int ldc = 0) {
    if (ldc == 0) ldc = N;
    dim3 grid(N / 128, (M + 127) / 128);
    if (act == 0) {
        cudaFuncSetAttribute(hgemm<0, OT>,
                             cudaFuncAttributeMaxDynamicSharedMemorySize, TG_SMEM);
        hgemm<0, OT><<<grid, 256, TG_SMEM>>>(A, W, bias, C, M, N, K, ldc);
    } else if (act == 1) {
        cudaFuncSetAttribute(hgemm<1, OT>,
                             cudaFuncAttributeMaxDynamicSharedMemorySize, TG_SMEM);
        hgemm<1, OT><<<grid, 256, TG_SMEM>>>(A, W, bias, C, M, N, K, ldc);
    } else {
        cudaFuncSetAttribute(hgemm<2, OT>,
                             cudaFuncAttributeMaxDynamicSharedMemorySize, TG_SMEM);
        hgemm<2, OT><<<grid, 256, TG_SMEM>>>(A, W, bias, C, M, N, K, ldc);
    }
}

extern "C" void kernel_launch(void* const* d_in, const int* in_sizes, int n_in,
                              void* d_out, int out_size) {
    const float* video = (const float*)d_in[0];
    const float* para = (const float*)d_in[1];
    const float* question = (const float*)d_in[2];
    const float* a_texts = (const float*)d_in[3];
    const float* a_buttons = (const float*)d_in[4];
    const float* paras_score = (const float*)d_in[5];
    const int* starts = (const int*)d_in[6];
    const int* ends = (const int*)d_in[7];
    const int* label = (const int*)d_in[8];
    const float* wv1 = (const float*)d_in[9];
    const float* bv1 = (const float*)d_in[10];
    const float* wv2 = (const float*)d_in[11];
    const float* bv2 = (const float*)d_in[12];
    const float* wt1 = (const float*)d_in[13];
    const float* bt1 = (const float*)d_in[14];
    const float* wt2 = (const float*)d_in[15];
    const float* bt2 = (const float*)d_in[16];
    const float* wp1 = (const float*)d_in[17];
    const float* bp1 = (const float*)d_in[18];
    const float* wp2 = (const float*)d_in[19];
    const float* bp2 = (const float*)d_in[20];
    const float* w_ih = (const float*)d_in[21];
    const float* b_ih = (const float*)d_in[22];
    const float* w_hh = (const float*)d_in[23];
    const float* b_hh = (const float*)d_in[24];
    const float* wq1 = (const float*)d_in[25];
    const float* bq1 = (const float*)d_in[26];
    const float* wq2 = (const float*)d_in[27];
    const float* bq2 = (const float*)d_in[28];
    const float* state0 = (const float*)d_in[29];
    float* out = (float*)d_out;

    float *p_score, *p_wts, *p_part, *p_vseg, *p_tq, *p_pre, *p_gi, *p_gh,
        *p_qh, *p_logits;
    cudaGetSymbolAddress((void**)&p_score, g_score);
    cudaGetSymbolAddress((void**)&p_wts, g_wts);
    cudaGetSymbolAddress((void**)&p_part, g_part);
    cudaGetSymbolAddress((void**)&p_vseg, g_vseg);
    cudaGetSymbolAddress((void**)&p_tq, g_tq);
    cudaGetSymbolAddress((void**)&p_pre, g_pre);
    cudaGetSymbolAddress((void**)&p_gi, g_gi);
    cudaGetSymbolAddress((void**)&p_gh, g_gh);
    cudaGetSymbolAddress((void**)&p_qh, g_qh);
    cudaGetSymbolAddress((void**)&p_logits, g_logits);

    bf16 *q_tin, *q_vin;
    bf16 *qw_v1, *qw_v2, *qw_t1, *qw_t2, *qw_p1, *qw_p2, *qw_ih, *qw_hh, *qw_q1;
    bf16 *q_h1t, *q_h1, *q_svid, *q_stxt, *q_comb, *q_preA, *q_xall, *q_hseq,
        *q_hnew;
    cudaGetSymbolAddress((void**)&q_tin, c_tin);
    cudaGetSymbolAddress((void**)&q_vin, c_vin);
    cudaGetSymbolAddress((void**)&qw_v1, b_wv1);
    cudaGetSymbolAddress((void**)&qw_v2, b_wv2);
    cudaGetSymbolAddress((void**)&qw_t1, b_wt1);
    cudaGetSymbolAddress((void**)&qw_t2, b_wt2);
    cudaGetSymbolAddress((void**)&qw_p1, b_wp1);
    cudaGetSymbolAddress((void**)&qw_p2, b_wp2);
    cudaGetSymbolAddress((void**)&qw_ih, b_wih);
    cudaGetSymbolAddress((void**)&qw_hh, b_whh);
    cudaGetSymbolAddress((void**)&qw_q1, b_wq1);
    cudaGetSymbolAddress((void**)&q_h1t, b_h1t);
    cudaGetSymbolAddress((void**)&q_h1, b_h1);
    cudaGetSymbolAddress((void**)&q_svid, b_svid);
    cudaGetSymbolAddress((void**)&q_stxt, b_stxt);
    cudaGetSymbolAddress((void**)&q_comb, b_comb);
    cudaGetSymbolAddress((void**)&q_preA, b_preA);
    cudaGetSymbolAddress((void**)&q_xall, b_xall);
    cudaGetSymbolAddress((void**)&q_hseq, b_hseq);
    cudaGetSymbolAddress((void**)&q_hnew, b_hnew);

    // 0. single fused fp32 -> bf16 conversion pass (inputs + weights)
    {
        CvtSegs cs;
        const float* srcs[NSEG] = {para, question, a_texts, video, a_buttons,
                                   wv1, wv2, wt1, wt2, wp1, wp2, w_ih, w_hh, wq1};
        bf16* dsts[NSEG] = {q_tin, q_tin + 768 * D_, q_tin + 784 * D_,
                            q_vin, q_vin + (size_t)16384 * D_,
                            qw_v1, qw_v2, qw_t1, qw_t2, qw_p1, qw_p2,
                            qw_ih, qw_hh, qw_q1};
        long long ns[NSEG] = {768 * D_, B_ * D_, NROWS * D_,
                              (long long)B_ * T_ * D_, (long long)NROWS * D_,
                              D_ * D_, D_ * D_, D_ * D_, D_ * D_,
                              (long long)4 * D_ * 4 * D_, (long long)4 * D_ * DS_,
                              (long long)DS_ * 3 * DS_, (long long)DS_ * 3 * DS_,
                              (long long)DS_ * DS_};
        long long acc = 0;
        for (int i = 0; i < NSEG; i++) {
            cs.src[i] = srcs[i];
            cs.dst[i] = dsts[i];
            cs.off[i] = acc;
            acc += ns[i];
        }
        cs.off[NSEG] = acc;
        long long nthreads = acc / 4;
        cvt_multi_kernel<<<(unsigned)((nthreads + 255) / 256), 256>>>(cs);
    }

    // 1. softmax over paragraph scores
    softmax_paras_kernel<<<1, 32>>>(paras_score, p_score);

    // 2. text L1 (merged [para|question|a_texts]); at L2 -> comb
    run_gemm(q_tin, qw_t1, bt1, q_h1t, TXT_ROWS, D_, D_, 1);
    run_gemm(q_h1t + (size_t)784 * D_, qw_t2, bt2, q_comb, NROWS, D_, D_, 0,
             1536);                                                        // at

    // 3. video L1 (merged [video|a_buttons]); ab L2 -> comb
    run_gemm(q_vin, qw_v1, bv1, q_h1, VID_ROWS, D_, D_, 1);
    run_gemm(q_h1 + (size_t)16384 * D_, qw_v2, bv2, q_comb + D_, NROWS, D_, D_,
             0, 1536);                                                     // ab

    // 4. segment weights + weighted reduces (linearity: reduce BEFORE layer 2)
    wts_kernel<<<B_, T_>>>(p_score, starts, ends, p_wts);
    wred_kernel<<<dim3(8, B_), D_>>>(p_wts, q_h1, p_part);
    vcomb_kernel<<<B_, D_>>>(p_part, q_svid);
    stxt_kernel<<<B_, D_>>>(p_score, q_h1t, q_stxt);

    // 5. tiny layer-2 GEMMs: vseg = svid@wv2+bv2 ; [tseg|q] = stxt@wt2+bt2
    run_gemm(q_svid, qw_v2, bv2, p_vseg, B_, D_, D_, 0);
    run_gemm(q_stxt, qw_t2, bt2, p_tq, 32, D_, D_, 0);

    // 6. fused row bias: preA = [vseg|tseg|q]; pre = preA @ wp1[0:2304] + bp1
    prea_kernel<<<B_, D_>>>(p_vseg, p_tq, q_preA);
    run_gemm(q_preA, qw_p1, bp1, p_pre, B_, 4 * D_, 3 * D_, 0);

    // 7. fusion MLP: layer1 = relu(comb @ wp1[2304:4608] + pre[row/288]) -> h1
    run_gemm(q_comb, qw_p1 + (size_t)(2 * D_) * (4 * D_), p_pre, q_h1,
             NROWS, 4 * D_, 2 * D_, 2);
    run_gemm(q_h1, qw_p2, bp2, q_xall, NROWS, DS_, 4 * D_, 0);

    // 8. teacher-forced hidden states + GRU gates
    hseq_kernel<<<S_ * B_, DS_>>>(q_xall, label, state0, q_hseq);
    run_gemm(q_xall, qw_ih, b_ih, p_gi, NROWS, 3 * DS_, DS_, 0);
    run_gemm(q_hseq, qw_hh, b_hh, p_gh, S_ * B_, 3 * DS_, DS_, 0);
    gru_kernel<<<NROWS, DS_>>>(p_gi, p_gh, q_hseq, q_hnew);

    // 9. logits MLP + loss
    run_gemm(q_hnew, qw_q1, bq1, p_qh, NROWS, DS_, DS_, 1);
    logits_kernel<<<(NROWS * 32 + 255) / 256, 256>>>(p_qh, wq2, bq2, p_logits);
    loss_kernel<<<1, S_ * B_>>>(p_logits, label, out);
}